// round 7
// baseline (speedup 1.0000x reference)
#include <cuda_runtime.h>
#include <cuda_fp16.h>
#include <cstdint>

// Problem constants
#define Bb 4
#define Ss 2048
#define Dd 1024
#define Hh 16
#define DHd 64
#define MM (Bb * Ss)          // 8192
#define N1 (3 * Dd)           // 3072

// ---------------- global scratch (fp16 hi/lo planes) ----------------
__device__ __half g_xhi[(size_t)MM * Dd];
__device__ __half g_xlo[(size_t)MM * Dd];
__device__ __half g_w1hi[(size_t)N1 * Dd];    // [n][k]
__device__ __half g_w1lo[(size_t)N1 * Dd];
__device__ __half g_w2hi[(size_t)Dd * Dd];    // [n][k]
__device__ __half g_w2lo[(size_t)Dd * Dd];    // written, never read (2-MMA)
__device__ __half g_qkvhi[(size_t)MM * N1];
__device__ __half g_qkvlo[(size_t)MM * N1];
__device__ __half g_ahi[(size_t)MM * Dd];
__device__ __half g_alo[(size_t)MM * Dd];

// ---------------- helpers ----------------
__device__ __forceinline__ uint32_t s2u(const void* p) {
    uint32_t a;
    asm("{ .reg .u64 t; cvta.to.shared.u64 t, %1; cvt.u32.u64 %0, t; }" : "=r"(a) : "l"(p));
    return a;
}
__device__ __forceinline__ void cp16(uint32_t saddr, const void* gaddr) {
    asm volatile("cp.async.cg.shared.global [%0], [%1], 16;" :: "r"(saddr), "l"(gaddr));
}
#define CP_COMMIT() asm volatile("cp.async.commit_group;" ::: "memory")
#define CP_WAIT0()  asm volatile("cp.async.wait_group 0;" ::: "memory")

__device__ __forceinline__ void ldmx4(uint32_t* r, uint32_t addr) {
    asm volatile("ldmatrix.sync.aligned.m8n8.x4.shared.b16 {%0,%1,%2,%3}, [%4];"
        : "=r"(r[0]), "=r"(r[1]), "=r"(r[2]), "=r"(r[3]) : "r"(addr));
}
__device__ __forceinline__ void ldmx4t(uint32_t* r, uint32_t addr) {
    asm volatile("ldmatrix.sync.aligned.m8n8.x4.trans.shared.b16 {%0,%1,%2,%3}, [%4];"
        : "=r"(r[0]), "=r"(r[1]), "=r"(r[2]), "=r"(r[3]) : "r"(addr));
}
__device__ __forceinline__ void mma_f16(float* c, const uint32_t* a, const uint32_t* b) {
    asm volatile("mma.sync.aligned.m16n8k16.row.col.f32.f16.f16.f32 "
        "{%0,%1,%2,%3}, {%4,%5,%6,%7}, {%8,%9}, {%0,%1,%2,%3};"
        : "+f"(c[0]), "+f"(c[1]), "+f"(c[2]), "+f"(c[3])
        : "r"(a[0]), "r"(a[1]), "r"(a[2]), "r"(a[3]), "r"(b[0]), "r"(b[1]));
}
// fp32 pair -> packed fp16 hi pair + fp16 lo pair (hi = rn(f), lo = rn(f - hi))
__device__ __forceinline__ void cvt_packh(float f0, float f1, uint32_t& hi, uint32_t& lo) {
    __half h0 = __float2half_rn(f0);
    __half h1 = __float2half_rn(f1);
    __half l0 = __float2half_rn(f0 - __half2float(h0));
    __half l1 = __float2half_rn(f1 - __half2float(h1));
    hi = ((uint32_t)__half_as_ushort(h1) << 16) | (uint32_t)__half_as_ushort(h0);
    lo = ((uint32_t)__half_as_ushort(l1) << 16) | (uint32_t)__half_as_ushort(l0);
}

// ---------------- pre-convert kernels ----------------
__global__ void __launch_bounds__(256) split_f32(
    const float* __restrict__ src, __half* __restrict__ hi,
    __half* __restrict__ lo, int n2)
{
    int i = blockIdx.x * 256 + threadIdx.x;
    if (i >= n2) return;
    float2 v = *(const float2*)(src + 2 * i);
    uint32_t h, l;
    cvt_packh(v.x, v.y, h, l);
    ((uint32_t*)hi)[i] = h;
    ((uint32_t*)lo)[i] = l;
}

// W[K][N] fp32 -> Wt hi/lo [N][K] fp16
__global__ void __launch_bounds__(256) transpose_split(
    const float* __restrict__ W, __half* __restrict__ Whi,
    __half* __restrict__ Wlo, int K, int N)
{
    __shared__ float sm[64][33];
    const int tid = threadIdx.x;
    const int n0 = blockIdx.x * 32;
    const int k0 = blockIdx.y * 64;
#pragma unroll
    for (int p = 0; p < 8; p++) {
        const int k = p * 8 + (tid >> 5);
        const int n = tid & 31;
        sm[k][n] = W[(size_t)(k0 + k) * N + n0 + n];
    }
    __syncthreads();
#pragma unroll
    for (int p = 0; p < 4; p++) {
        const int n = p * 8 + (tid >> 5);
        const int kp = tid & 31;
        uint32_t h, l;
        cvt_packh(sm[2 * kp][n], sm[2 * kp + 1][n], h, l);
        const size_t idx = ((size_t)(n0 + n) * K + k0) / 2 + kp;
        ((uint32_t*)Whi)[idx] = h;
        ((uint32_t*)Wlo)[idx] = l;
    }
}

// ---------------------------------------------------------------------------
// GEMM from fp16 planes. C = A @ B^T(+bias), A [M][K], B [N][K].
// 128x128 tile, BK=32, cp.async double-buffered, 8 warps (2m x 4n).
// 3-MMA when col0 < n3lim else 2-MMA.
// MMA issue interleaved across nt so same-accumulator distance = 4.
// ---------------------------------------------------------------------------
#define GST 80
#define GTILE (128 * GST)
#define GSTAGE (4 * GTILE)
#define GEMM_SMEM (2 * GSTAGE)

template<int EPI>
__global__ void __launch_bounds__(256, 2) gemm_hf(
    const __half* __restrict__ Ahi, const __half* __restrict__ Alo,
    const __half* __restrict__ Bhi, const __half* __restrict__ Blo,
    const float* __restrict__ bias, float* __restrict__ Cf,
    __half* __restrict__ Chi, __half* __restrict__ Clo,
    int M, int N, int K, int n3lim)
{
    extern __shared__ char smem[];
    const int tid = threadIdx.x;
    const int lane = tid & 31;
    const int warp = tid >> 5;
    const int wm = warp >> 2;
    const int wn = warp & 3;
    const int row0 = blockIdx.y * 128;
    const int col0 = blockIdx.x * 128;
    const bool use3 = (col0 < n3lim);

    const int lrow = tid >> 1;
    const int lq = (tid & 1) * 2;

    auto issue = [&](int kc, int s) {
        char* stg = smem + s * GSTAGE;
        const uint32_t sA = s2u(stg) + (uint32_t)lrow * GST + lq * 16;
        const size_t gOffA = (size_t)(row0 + lrow) * K + kc * 32 + lq * 8;
        cp16(sA, Ahi + gOffA);
        cp16(sA + 16, Ahi + gOffA + 8);
        cp16(sA + GTILE, Alo + gOffA);
        cp16(sA + GTILE + 16, Alo + gOffA + 8);
        const size_t gOffB = (size_t)(col0 + lrow) * K + kc * 32 + lq * 8;
        cp16(sA + 2 * GTILE, Bhi + gOffB);
        cp16(sA + 2 * GTILE + 16, Bhi + gOffB + 8);
        if (use3) {
            cp16(sA + 3 * GTILE, Blo + gOffB);
            cp16(sA + 3 * GTILE + 16, Blo + gOffB + 8);
        }
    };

    float acc[4][4][4];
#pragma unroll
    for (int i = 0; i < 4; i++)
#pragma unroll
        for (int j = 0; j < 4; j++)
#pragma unroll
            for (int e = 0; e < 4; e++) acc[i][j][e] = 0.f;

    const uint32_t fragoff = (uint32_t)(lane & 15) * GST + (uint32_t)(lane >> 4) * 16;

    issue(0, 0);
    CP_COMMIT();

    const int nch = K / 32;
    for (int kc = 0; kc < nch; kc++) {
        const int s = kc & 1;
        CP_WAIT0();
        __syncthreads();
        if (kc + 1 < nch) {
            issue(kc + 1, s ^ 1);
            CP_COMMIT();
        }
        char* stg = smem + s * GSTAGE;
        const uint32_t uAhi = s2u(stg);
        const uint32_t uAlo = uAhi + GTILE;
        const uint32_t uBhi = uAhi + 2 * GTILE;
        const uint32_t uBlo = uAhi + 3 * GTILE;

#pragma unroll
        for (int ks = 0; ks < 2; ks++) {
            const uint32_t kb = (uint32_t)ks * 32;
            uint32_t bh[4][2], bl[4][2];
#pragma unroll
            for (int ntp = 0; ntp < 2; ntp++) {
                const uint32_t boff = (uint32_t)(wn * 32 + ntp * 16) * GST + kb + fragoff;
                uint32_t m[4];
                ldmx4(m, uBhi + boff);
                bh[ntp * 2 + 0][0] = m[0]; bh[ntp * 2 + 1][0] = m[1];
                bh[ntp * 2 + 0][1] = m[2]; bh[ntp * 2 + 1][1] = m[3];
                if (use3) {
                    ldmx4(m, uBlo + boff);
                    bl[ntp * 2 + 0][0] = m[0]; bl[ntp * 2 + 1][0] = m[1];
                    bl[ntp * 2 + 0][1] = m[2]; bl[ntp * 2 + 1][1] = m[3];
                }
            }
#pragma unroll
            for (int mt = 0; mt < 4; mt++) {
                const uint32_t aoff = (uint32_t)(wm * 64 + mt * 16) * GST + kb + fragoff;
                uint32_t ah[4], al[4];
                ldmx4(ah, uAhi + aoff);
                ldmx4(al, uAlo + aoff);
                // interleave: same-acc distance 4 instead of 1
#pragma unroll
                for (int nt = 0; nt < 4; nt++) mma_f16(acc[mt][nt], ah, bh[nt]);
                if (use3) {
#pragma unroll
                    for (int nt = 0; nt < 4; nt++) mma_f16(acc[mt][nt], ah, bl[nt]);
                }
#pragma unroll
                for (int nt = 0; nt < 4; nt++) mma_f16(acc[mt][nt], al, bh[nt]);
            }
        }
    }

    // epilogue
#pragma unroll
    for (int mt = 0; mt < 4; mt++) {
        const int r = row0 + wm * 64 + mt * 16 + (lane >> 2);
#pragma unroll
        for (int nt = 0; nt < 4; nt++) {
            const int c = col0 + wn * 32 + nt * 8 + (lane & 3) * 2;
            const float bx = bias[c];
            const float by = bias[c + 1];
            const float f0 = acc[mt][nt][0] + bx;
            const float f1 = acc[mt][nt][1] + by;
            const float f2 = acc[mt][nt][2] + bx;
            const float f3 = acc[mt][nt][3] + by;
            if (EPI == 0) {
                *(float2*)(Cf + (size_t)r * N + c) = make_float2(f0, f1);
                *(float2*)(Cf + (size_t)(r + 8) * N + c) = make_float2(f2, f3);
            } else {
                uint32_t h0, l0, h1, l1;
                cvt_packh(f0, f1, h0, l0);
                cvt_packh(f2, f3, h1, l1);
                const size_t i0 = ((size_t)r * N + c) / 2;
                const size_t i1 = ((size_t)(r + 8) * N + c) / 2;
                ((uint32_t*)Chi)[i0] = h0; ((uint32_t*)Clo)[i0] = l0;
                ((uint32_t*)Chi)[i1] = h1; ((uint32_t*)Clo)[i1] = l1;
            }
        }
    }
}

// ---------------------------------------------------------------------------
// Flash attention from fp16 qkv planes. QK: 3-MMA; PV: 2-MMA (Vlo never loaded).
// MMA issue alternates accumulator tiles (distance >= 2).
// ---------------------------------------------------------------------------
#define AST 144
#define ATL (64 * AST)
#define ASTG (3 * ATL)              // Khi,Klo,Vhi = 27648
#define ATTN_SMEM (ASTG + 2 * 128 * AST)   // 64512

__global__ void __launch_bounds__(256) flash2(
    const __half* __restrict__ qhi, const __half* __restrict__ qlo,
    __half* __restrict__ ohi, __half* __restrict__ olo)
{
    extern __shared__ char smem[];
    const int tid = threadIdx.x;
    const int lane = tid & 31;
    const int warp = tid >> 5;
    const int qt = blockIdx.x;
    const int bh = blockIdx.y;
    const int b = bh >> 4;
    const int h = bh & 15;

    const uint32_t sb = s2u(smem);
    const uint32_t fragoff = (uint32_t)(lane & 15) * AST + (uint32_t)(lane >> 4) * 16;
    const size_t headoff = (size_t)h * DHd;

    const int krow = tid >> 2;
    const int kcc = (tid & 3) * 2;
    auto issueKV = [&](int kb, int s) {
        const uint32_t sB = sb + s * ASTG + (uint32_t)krow * AST + kcc * 16;
        const size_t g = ((size_t)b * Ss + kb * 64 + krow) * N1 + headoff + kcc * 8;
        cp16(sB,                 qhi + g + Dd);       // K hi
        cp16(sB + 16,            qhi + g + Dd + 8);
        cp16(sB + ATL,           qlo + g + Dd);       // K lo
        cp16(sB + ATL + 16,      qlo + g + Dd + 8);
        cp16(sB + 2 * ATL,       qhi + g + 2 * Dd);   // V hi
        cp16(sB + 2 * ATL + 16,  qhi + g + 2 * Dd + 8);
    };

    // preload: K/V block0 -> stage0; Q -> region above stage0 (overlaps stage1,
    // safe: Q is consumed into registers before stage1 is first written)
    issueKV(0, 0);
    CP_COMMIT();
    {
        const int qrow = tid >> 1;
        const int q4 = (tid & 1) * 4;
        const uint32_t sQh = sb + ASTG + (uint32_t)qrow * AST + q4 * 16;
        const uint32_t sQl = sQh + 128 * AST;
        const size_t g = ((size_t)b * Ss + qt * 128 + qrow) * N1 + headoff + q4 * 8;
#pragma unroll
        for (int i = 0; i < 4; i++) {
            cp16(sQh + i * 16, qhi + g + i * 8);
            cp16(sQl + i * 16, qlo + g + i * 8);
        }
    }
    CP_COMMIT();
    CP_WAIT0();
    __syncthreads();

    // Q fragments (extracted before stage1 is ever written)
    uint32_t qh[4][4], ql[4][4];
    {
        const uint32_t uQh = sb + ASTG;
        const uint32_t uQl = uQh + 128 * AST;
#pragma unroll
        for (int j = 0; j < 4; j++) {
            const uint32_t aoff = (uint32_t)(warp * 16) * AST + j * 32 + fragoff;
            ldmx4(qh[j], uQh + aoff);
            ldmx4(ql[j], uQl + aoff);
        }
    }

    float o[8][4];
    float m0 = -1e30f, m1 = -1e30f, l0 = 0.f, l1 = 0.f;
#pragma unroll
    for (int i = 0; i < 8; i++)
#pragma unroll
        for (int e = 0; e < 4; e++) o[i][e] = 0.f;

    for (int kb = 0; kb < Ss / 64; kb++) {
        const int s = kb & 1;
        if (kb > 0) CP_WAIT0();
        __syncthreads();
        if (kb + 1 < Ss / 64) {
            issueKV(kb + 1, s ^ 1);
            CP_COMMIT();
        }
        const uint32_t uKhi = sb + s * ASTG;
        const uint32_t uKlo = uKhi + ATL;
        const uint32_t uVhi = uKhi + 2 * ATL;

        // ---- S = Q K^T (3-MMA, alternating accumulators) ----
        float sc[8][4];
#pragma unroll
        for (int i = 0; i < 8; i++)
#pragma unroll
            for (int e = 0; e < 4; e++) sc[i][e] = 0.f;

#pragma unroll
        for (int g = 0; g < 4; g++) {
#pragma unroll
            for (int j = 0; j < 4; j++) {
                const uint32_t boff = (uint32_t)(g * 16) * AST + j * 32 + fragoff;
                uint32_t mh[4], ml[4];
                ldmx4(mh, uKhi + boff);
                ldmx4(ml, uKlo + boff);
                uint32_t b0h[2] = {mh[0], mh[2]}, b1h[2] = {mh[1], mh[3]};
                uint32_t b0l[2] = {ml[0], ml[2]}, b1l[2] = {ml[1], ml[3]};
                mma_f16(sc[2 * g + 0], qh[j], b0h);
                mma_f16(sc[2 * g + 1], qh[j], b1h);
                mma_f16(sc[2 * g + 0], qh[j], b0l);
                mma_f16(sc[2 * g + 1], qh[j], b1l);
                mma_f16(sc[2 * g + 0], ql[j], b0h);
                mma_f16(sc[2 * g + 1], ql[j], b1h);
            }
        }

        // ---- online softmax ----
        float mx0 = -1e30f, mx1 = -1e30f;
#pragma unroll
        for (int i = 0; i < 8; i++) {
            mx0 = fmaxf(mx0, fmaxf(sc[i][0], sc[i][1]));
            mx1 = fmaxf(mx1, fmaxf(sc[i][2], sc[i][3]));
        }
        mx0 = fmaxf(mx0, __shfl_xor_sync(0xffffffffu, mx0, 1));
        mx0 = fmaxf(mx0, __shfl_xor_sync(0xffffffffu, mx0, 2));
        mx1 = fmaxf(mx1, __shfl_xor_sync(0xffffffffu, mx1, 1));
        mx1 = fmaxf(mx1, __shfl_xor_sync(0xffffffffu, mx1, 2));
        const float mn0 = fmaxf(m0, mx0);
        const float mn1 = fmaxf(m1, mx1);
        const float c0 = __expf(m0 - mn0);
        const float c1 = __expf(m1 - mn1);
        float rs0 = 0.f, rs1 = 0.f;
#pragma unroll
        for (int i = 0; i < 8; i++) {
            sc[i][0] = __expf(sc[i][0] - mn0);
            sc[i][1] = __expf(sc[i][1] - mn0);
            sc[i][2] = __expf(sc[i][2] - mn1);
            sc[i][3] = __expf(sc[i][3] - mn1);
            rs0 += sc[i][0] + sc[i][1];
            rs1 += sc[i][2] + sc[i][3];
        }
        rs0 += __shfl_xor_sync(0xffffffffu, rs0, 1);
        rs0 += __shfl_xor_sync(0xffffffffu, rs0, 2);
        rs1 += __shfl_xor_sync(0xffffffffu, rs1, 1);
        rs1 += __shfl_xor_sync(0xffffffffu, rs1, 2);
        l0 = l0 * c0 + rs0;
        l1 = l1 * c1 + rs1;
        m0 = mn0;
        m1 = mn1;
#pragma unroll
        for (int i = 0; i < 8; i++) {
            o[i][0] *= c0; o[i][1] *= c0;
            o[i][2] *= c1; o[i][3] *= c1;
        }

        // ---- repack P (C-frag -> A-frag), hi/lo fp16 ----
        uint32_t ph[4][4], pl[4][4];
#pragma unroll
        for (int j = 0; j < 4; j++) {
            cvt_packh(sc[2 * j][0],     sc[2 * j][1],     ph[j][0], pl[j][0]);
            cvt_packh(sc[2 * j][2],     sc[2 * j][3],     ph[j][1], pl[j][1]);
            cvt_packh(sc[2 * j + 1][0], sc[2 * j + 1][1], ph[j][2], pl[j][2]);
            cvt_packh(sc[2 * j + 1][2], sc[2 * j + 1][3], ph[j][3], pl[j][3]);
        }

        // ---- O += P V (2-MMA, alternating accumulators) ----
#pragma unroll
        for (int g = 0; g < 4; g++) {
#pragma unroll
            for (int j = 0; j < 4; j++) {
                const uint32_t voff = (uint32_t)(j * 16) * AST + g * 32 + fragoff;
                uint32_t mh[4];
                ldmx4t(mh, uVhi + voff);
                uint32_t b0h[2] = {mh[0], mh[1]}, b1h[2] = {mh[2], mh[3]};
                mma_f16(o[2 * g + 0], ph[j], b0h);
                mma_f16(o[2 * g + 1], ph[j], b1h);
                mma_f16(o[2 * g + 0], pl[j], b0h);
                mma_f16(o[2 * g + 1], pl[j], b1h);
            }
        }
    }

    // ---- epilogue: write fp16 hi/lo planes ----
    const float inv0 = 1.f / l0;
    const float inv1 = 1.f / l1;
    const int r0 = qt * 128 + warp * 16 + (lane >> 2);
    const size_t base0 = ((size_t)b * Ss + r0) * Dd + headoff + (lane & 3) * 2;
    const size_t base1 = base0 + (size_t)8 * Dd;
#pragma unroll
    for (int nt = 0; nt < 8; nt++) {
        uint32_t h0, l0u, h1, l1u;
        cvt_packh(o[nt][0] * inv0, o[nt][1] * inv0, h0, l0u);
        cvt_packh(o[nt][2] * inv1, o[nt][3] * inv1, h1, l1u);
        ((uint32_t*)ohi)[(base0 + nt * 8) / 2] = h0;
        ((uint32_t*)olo)[(base0 + nt * 8) / 2] = l0u;
        ((uint32_t*)ohi)[(base1 + nt * 8) / 2] = h1;
        ((uint32_t*)olo)[(base1 + nt * 8) / 2] = l1u;
    }
}

// ---------------------------------------------------------------------------
extern "C" void kernel_launch(void* const* d_in, const int* in_sizes, int n_in,
                              void* d_out, int out_size)
{
    (void)in_sizes; (void)n_in; (void)out_size;
    const float* x  = (const float*)d_in[0];
    const float* w1 = (const float*)d_in[1];
    const float* b1 = (const float*)d_in[2];
    const float* w2 = (const float*)d_in[3];
    const float* b2 = (const float*)d_in[4];
    float* out = (float*)d_out;

    __half *xhi, *xlo, *w1hi, *w1lo, *w2hi, *w2lo, *qhi, *qlo, *ahi, *alo;
    cudaGetSymbolAddress((void**)&xhi, g_xhi);
    cudaGetSymbolAddress((void**)&xlo, g_xlo);
    cudaGetSymbolAddress((void**)&w1hi, g_w1hi);
    cudaGetSymbolAddress((void**)&w1lo, g_w1lo);
    cudaGetSymbolAddress((void**)&w2hi, g_w2hi);
    cudaGetSymbolAddress((void**)&w2lo, g_w2lo);
    cudaGetSymbolAddress((void**)&qhi, g_qkvhi);
    cudaGetSymbolAddress((void**)&qlo, g_qkvlo);
    cudaGetSymbolAddress((void**)&ahi, g_ahi);
    cudaGetSymbolAddress((void**)&alo, g_alo);

    cudaFuncSetAttribute(gemm_hf<0>, cudaFuncAttributeMaxDynamicSharedMemorySize, GEMM_SMEM);
    cudaFuncSetAttribute(gemm_hf<1>, cudaFuncAttributeMaxDynamicSharedMemorySize, GEMM_SMEM);
    cudaFuncSetAttribute(flash2, cudaFuncAttributeMaxDynamicSharedMemorySize, ATTN_SMEM);

    // pre-convert
    split_f32<<<(MM * Dd / 2 + 255) / 256, 256>>>(x, xhi, xlo, MM * Dd / 2);
    transpose_split<<<dim3(N1 / 32, Dd / 64), 256>>>(w1, w1hi, w1lo, Dd, N1);
    transpose_split<<<dim3(Dd / 32, Dd / 64), 256>>>(w2, w2hi, w2lo, Dd, Dd);

    // 1) QKV projection -> fp16 planes (Q,K cols: 3-MMA; V cols: 2-MMA)
    gemm_hf<1><<<dim3(N1 / 128, MM / 128), 256, GEMM_SMEM>>>(
        xhi, xlo, w1hi, w1lo, b1, nullptr, qhi, qlo, MM, N1, Dd, 2 * Dd);
    // 2) attention -> fp16 planes
    flash2<<<dim3(Ss / 128, Bb * Hh), 256, ATTN_SMEM>>>(qhi, qlo, ahi, alo);
    // 3) output projection (2-MMA) -> fp32 out
    gemm_hf<0><<<dim3(Dd / 128, MM / 128), 256, GEMM_SMEM>>>(
        ahi, alo, w2hi, w2lo, b2, out, nullptr, nullptr, MM, Dd, Dd, 0);
}

// round 8
// speedup vs baseline: 1.0837x; 1.0837x over previous
#include <cuda_runtime.h>
#include <cuda_fp16.h>
#include <cstdint>

// Problem constants
#define Bb 4
#define Ss 2048
#define Dd 1024
#define Hh 16
#define DHd 64
#define MM (Bb * Ss)          // 8192
#define N1 (3 * Dd)           // 3072

// ---------------- global scratch (fp16 hi/lo planes) ----------------
__device__ __half g_xhi[(size_t)MM * Dd];
__device__ __half g_xlo[(size_t)MM * Dd];
__device__ __half g_w1hi[(size_t)N1 * Dd];    // [n][k]
__device__ __half g_w1lo[(size_t)N1 * Dd];
__device__ __half g_w2hi[(size_t)Dd * Dd];    // [n][k]
__device__ __half g_w2lo[(size_t)Dd * Dd];    // written, never read (2-MMA)
__device__ __half g_qkvhi[(size_t)MM * N1];
__device__ __half g_qkvlo[(size_t)MM * N1];
__device__ __half g_ahi[(size_t)MM * Dd];
__device__ __half g_alo[(size_t)MM * Dd];

// ---------------- helpers ----------------
__device__ __forceinline__ uint32_t s2u(const void* p) {
    uint32_t a;
    asm("{ .reg .u64 t; cvta.to.shared.u64 t, %1; cvt.u32.u64 %0, t; }" : "=r"(a) : "l"(p));
    return a;
}
__device__ __forceinline__ void cp16(uint32_t saddr, const void* gaddr) {
    asm volatile("cp.async.cg.shared.global [%0], [%1], 16;" :: "r"(saddr), "l"(gaddr));
}
#define CP_COMMIT() asm volatile("cp.async.commit_group;" ::: "memory")
#define CP_WAIT0()  asm volatile("cp.async.wait_group 0;" ::: "memory")

__device__ __forceinline__ void ldmx4(uint32_t* r, uint32_t addr) {
    asm volatile("ldmatrix.sync.aligned.m8n8.x4.shared.b16 {%0,%1,%2,%3}, [%4];"
        : "=r"(r[0]), "=r"(r[1]), "=r"(r[2]), "=r"(r[3]) : "r"(addr));
}
__device__ __forceinline__ void ldmx4t(uint32_t* r, uint32_t addr) {
    asm volatile("ldmatrix.sync.aligned.m8n8.x4.trans.shared.b16 {%0,%1,%2,%3}, [%4];"
        : "=r"(r[0]), "=r"(r[1]), "=r"(r[2]), "=r"(r[3]) : "r"(addr));
}
__device__ __forceinline__ void mma_f16(float* c, const uint32_t* a, const uint32_t* b) {
    asm volatile("mma.sync.aligned.m16n8k16.row.col.f32.f16.f16.f32 "
        "{%0,%1,%2,%3}, {%4,%5,%6,%7}, {%8,%9}, {%0,%1,%2,%3};"
        : "+f"(c[0]), "+f"(c[1]), "+f"(c[2]), "+f"(c[3])
        : "r"(a[0]), "r"(a[1]), "r"(a[2]), "r"(a[3]), "r"(b[0]), "r"(b[1]));
}
// fp32 pair -> packed fp16 hi pair + fp16 lo pair (hi = rn(f), lo = rn(f - hi))
__device__ __forceinline__ void cvt_packh(float f0, float f1, uint32_t& hi, uint32_t& lo) {
    __half h0 = __float2half_rn(f0);
    __half h1 = __float2half_rn(f1);
    __half l0 = __float2half_rn(f0 - __half2float(h0));
    __half l1 = __float2half_rn(f1 - __half2float(h1));
    hi = ((uint32_t)__half_as_ushort(h1) << 16) | (uint32_t)__half_as_ushort(h0);
    lo = ((uint32_t)__half_as_ushort(l1) << 16) | (uint32_t)__half_as_ushort(l0);
}

// ---------------- pre-convert kernels ----------------
__global__ void __launch_bounds__(256) split_f32(
    const float* __restrict__ src, __half* __restrict__ hi,
    __half* __restrict__ lo, int n2)
{
    int i = blockIdx.x * 256 + threadIdx.x;
    if (i >= n2) return;
    float2 v = *(const float2*)(src + 2 * i);
    uint32_t h, l;
    cvt_packh(v.x, v.y, h, l);
    ((uint32_t*)hi)[i] = h;
    ((uint32_t*)lo)[i] = l;
}

// W[K][N] fp32 -> Wt hi/lo [N][K] fp16
__global__ void __launch_bounds__(256) transpose_split(
    const float* __restrict__ W, __half* __restrict__ Whi,
    __half* __restrict__ Wlo, int K, int N)
{
    __shared__ float sm[64][33];
    const int tid = threadIdx.x;
    const int n0 = blockIdx.x * 32;
    const int k0 = blockIdx.y * 64;
#pragma unroll
    for (int p = 0; p < 8; p++) {
        const int k = p * 8 + (tid >> 5);
        const int n = tid & 31;
        sm[k][n] = W[(size_t)(k0 + k) * N + n0 + n];
    }
    __syncthreads();
#pragma unroll
    for (int p = 0; p < 4; p++) {
        const int n = p * 8 + (tid >> 5);
        const int kp = tid & 31;
        uint32_t h, l;
        cvt_packh(sm[2 * kp][n], sm[2 * kp + 1][n], h, l);
        const size_t idx = ((size_t)(n0 + n) * K + k0) / 2 + kp;
        ((uint32_t*)Whi)[idx] = h;
        ((uint32_t*)Wlo)[idx] = l;
    }
}

// ---------------------------------------------------------------------------
// GEMM from fp16 planes. C = A @ B^T(+bias), A [M][K], B [N][K].
// 128x128 tile, BK=32, cp.async double-buffered, 8 warps (2m x 4n).
// 3-MMA when col0 < n3lim else 2-MMA.
// PASS-MAJOR MMA order: same-accumulator reuse distance = 16 issues.
// ---------------------------------------------------------------------------
#define GST 80
#define GTILE (128 * GST)
#define GSTAGE (4 * GTILE)
#define GEMM_SMEM (2 * GSTAGE)

template<int EPI>
__global__ void __launch_bounds__(256, 2) gemm_hf(
    const __half* __restrict__ Ahi, const __half* __restrict__ Alo,
    const __half* __restrict__ Bhi, const __half* __restrict__ Blo,
    const float* __restrict__ bias, float* __restrict__ Cf,
    __half* __restrict__ Chi, __half* __restrict__ Clo,
    int M, int N, int K, int n3lim)
{
    extern __shared__ char smem[];
    const int tid = threadIdx.x;
    const int lane = tid & 31;
    const int warp = tid >> 5;
    const int wm = warp >> 2;
    const int wn = warp & 3;
    const int row0 = blockIdx.y * 128;
    const int col0 = blockIdx.x * 128;
    const bool use3 = (col0 < n3lim);

    const int lrow = tid >> 1;
    const int lq = (tid & 1) * 2;

    auto issue = [&](int kc, int s) {
        char* stg = smem + s * GSTAGE;
        const uint32_t sA = s2u(stg) + (uint32_t)lrow * GST + lq * 16;
        const size_t gOffA = (size_t)(row0 + lrow) * K + kc * 32 + lq * 8;
        cp16(sA, Ahi + gOffA);
        cp16(sA + 16, Ahi + gOffA + 8);
        cp16(sA + GTILE, Alo + gOffA);
        cp16(sA + GTILE + 16, Alo + gOffA + 8);
        const size_t gOffB = (size_t)(col0 + lrow) * K + kc * 32 + lq * 8;
        cp16(sA + 2 * GTILE, Bhi + gOffB);
        cp16(sA + 2 * GTILE + 16, Bhi + gOffB + 8);
        if (use3) {
            cp16(sA + 3 * GTILE, Blo + gOffB);
            cp16(sA + 3 * GTILE + 16, Blo + gOffB + 8);
        }
    };

    float acc[4][4][4];
#pragma unroll
    for (int i = 0; i < 4; i++)
#pragma unroll
        for (int j = 0; j < 4; j++)
#pragma unroll
            for (int e = 0; e < 4; e++) acc[i][j][e] = 0.f;

    const uint32_t fragoff = (uint32_t)(lane & 15) * GST + (uint32_t)(lane >> 4) * 16;

    issue(0, 0);
    CP_COMMIT();

    const int nch = K / 32;
    for (int kc = 0; kc < nch; kc++) {
        const int s = kc & 1;
        CP_WAIT0();
        __syncthreads();
        if (kc + 1 < nch) {
            issue(kc + 1, s ^ 1);
            CP_COMMIT();
        }
        char* stg = smem + s * GSTAGE;
        const uint32_t uAhi = s2u(stg);
        const uint32_t uAlo = uAhi + GTILE;
        const uint32_t uBhi = uAhi + 2 * GTILE;
        const uint32_t uBlo = uAhi + 3 * GTILE;

#pragma unroll
        for (int ks = 0; ks < 2; ks++) {
            const uint32_t kb = (uint32_t)ks * 32;
            // B fragments
            uint32_t bh[4][2], bl[4][2];
#pragma unroll
            for (int ntp = 0; ntp < 2; ntp++) {
                const uint32_t boff = (uint32_t)(wn * 32 + ntp * 16) * GST + kb + fragoff;
                uint32_t m[4];
                ldmx4(m, uBhi + boff);
                bh[ntp * 2 + 0][0] = m[0]; bh[ntp * 2 + 1][0] = m[1];
                bh[ntp * 2 + 0][1] = m[2]; bh[ntp * 2 + 1][1] = m[3];
                if (use3) {
                    ldmx4(m, uBlo + boff);
                    bl[ntp * 2 + 0][0] = m[0]; bl[ntp * 2 + 1][0] = m[1];
                    bl[ntp * 2 + 0][1] = m[2]; bl[ntp * 2 + 1][1] = m[3];
                }
            }
            // Stage all A-hi fragments for this k-step
            uint32_t ah[4][4];
#pragma unroll
            for (int mt = 0; mt < 4; mt++) {
                const uint32_t aoff = (uint32_t)(wm * 64 + mt * 16) * GST + kb + fragoff;
                ldmx4(ah[mt], uAhi + aoff);
            }
            // PASS 1: ah·bh — each acc touched once per 16 issues
#pragma unroll
            for (int mt = 0; mt < 4; mt++)
#pragma unroll
                for (int nt = 0; nt < 4; nt++)
                    mma_f16(acc[mt][nt], ah[mt], bh[nt]);
            // PASS 2: ah·bl
            if (use3) {
#pragma unroll
                for (int mt = 0; mt < 4; mt++)
#pragma unroll
                    for (int nt = 0; nt < 4; nt++)
                        mma_f16(acc[mt][nt], ah[mt], bl[nt]);
            }
            // PASS 3: al·bh (al loaded per-mt; acc distance stays >= 12)
#pragma unroll
            for (int mt = 0; mt < 4; mt++) {
                const uint32_t aoff = (uint32_t)(wm * 64 + mt * 16) * GST + kb + fragoff;
                uint32_t al[4];
                ldmx4(al, uAlo + aoff);
#pragma unroll
                for (int nt = 0; nt < 4; nt++)
                    mma_f16(acc[mt][nt], al, bh[nt]);
            }
        }
    }

    // epilogue
#pragma unroll
    for (int mt = 0; mt < 4; mt++) {
        const int r = row0 + wm * 64 + mt * 16 + (lane >> 2);
#pragma unroll
        for (int nt = 0; nt < 4; nt++) {
            const int c = col0 + wn * 32 + nt * 8 + (lane & 3) * 2;
            const float bx = bias[c];
            const float by = bias[c + 1];
            const float f0 = acc[mt][nt][0] + bx;
            const float f1 = acc[mt][nt][1] + by;
            const float f2 = acc[mt][nt][2] + bx;
            const float f3 = acc[mt][nt][3] + by;
            if (EPI == 0) {
                *(float2*)(Cf + (size_t)r * N + c) = make_float2(f0, f1);
                *(float2*)(Cf + (size_t)(r + 8) * N + c) = make_float2(f2, f3);
            } else {
                uint32_t h0, l0, h1, l1;
                cvt_packh(f0, f1, h0, l0);
                cvt_packh(f2, f3, h1, l1);
                const size_t i0 = ((size_t)r * N + c) / 2;
                const size_t i1 = ((size_t)(r + 8) * N + c) / 2;
                ((uint32_t*)Chi)[i0] = h0; ((uint32_t*)Clo)[i0] = l0;
                ((uint32_t*)Chi)[i1] = h1; ((uint32_t*)Clo)[i1] = l1;
            }
        }
    }
}

// ---------------------------------------------------------------------------
// Flash attention from fp16 qkv planes. QK: 3-MMA; PV: 2-MMA (Vlo never loaded).
// PASS-MAJOR MMA order: accumulator reuse distance = 8 issues (was 2).
// ---------------------------------------------------------------------------
#define AST 144
#define ATL (64 * AST)
#define ASTG (3 * ATL)              // Khi,Klo,Vhi = 27648
#define ATTN_SMEM (ASTG + 2 * 128 * AST)   // 64512

__global__ void __launch_bounds__(256) flash2(
    const __half* __restrict__ qhi, const __half* __restrict__ qlo,
    __half* __restrict__ ohi, __half* __restrict__ olo)
{
    extern __shared__ char smem[];
    const int tid = threadIdx.x;
    const int lane = tid & 31;
    const int warp = tid >> 5;
    const int qt = blockIdx.x;
    const int bh = blockIdx.y;
    const int b = bh >> 4;
    const int h = bh & 15;

    const uint32_t sb = s2u(smem);
    const uint32_t fragoff = (uint32_t)(lane & 15) * AST + (uint32_t)(lane >> 4) * 16;
    const size_t headoff = (size_t)h * DHd;

    const int krow = tid >> 2;
    const int kcc = (tid & 3) * 2;
    auto issueKV = [&](int kb, int s) {
        const uint32_t sB = sb + s * ASTG + (uint32_t)krow * AST + kcc * 16;
        const size_t g = ((size_t)b * Ss + kb * 64 + krow) * N1 + headoff + kcc * 8;
        cp16(sB,                 qhi + g + Dd);       // K hi
        cp16(sB + 16,            qhi + g + Dd + 8);
        cp16(sB + ATL,           qlo + g + Dd);       // K lo
        cp16(sB + ATL + 16,      qlo + g + Dd + 8);
        cp16(sB + 2 * ATL,       qhi + g + 2 * Dd);   // V hi
        cp16(sB + 2 * ATL + 16,  qhi + g + 2 * Dd + 8);
    };

    // preload: K/V block0 -> stage0; Q -> region above stage0 (overlaps stage1,
    // safe: Q is consumed into registers before stage1 is first written)
    issueKV(0, 0);
    CP_COMMIT();
    {
        const int qrow = tid >> 1;
        const int q4 = (tid & 1) * 4;
        const uint32_t sQh = sb + ASTG + (uint32_t)qrow * AST + q4 * 16;
        const uint32_t sQl = sQh + 128 * AST;
        const size_t g = ((size_t)b * Ss + qt * 128 + qrow) * N1 + headoff + q4 * 8;
#pragma unroll
        for (int i = 0; i < 4; i++) {
            cp16(sQh + i * 16, qhi + g + i * 8);
            cp16(sQl + i * 16, qlo + g + i * 8);
        }
    }
    CP_COMMIT();
    CP_WAIT0();
    __syncthreads();

    // Q fragments (extracted before stage1 is ever written)
    uint32_t qh[4][4], ql[4][4];
    {
        const uint32_t uQh = sb + ASTG;
        const uint32_t uQl = uQh + 128 * AST;
#pragma unroll
        for (int j = 0; j < 4; j++) {
            const uint32_t aoff = (uint32_t)(warp * 16) * AST + j * 32 + fragoff;
            ldmx4(qh[j], uQh + aoff);
            ldmx4(ql[j], uQl + aoff);
        }
    }

    float o[8][4];
    float m0 = -1e30f, m1 = -1e30f, l0 = 0.f, l1 = 0.f;
#pragma unroll
    for (int i = 0; i < 8; i++)
#pragma unroll
        for (int e = 0; e < 4; e++) o[i][e] = 0.f;

    for (int kb = 0; kb < Ss / 64; kb++) {
        const int s = kb & 1;
        if (kb > 0) CP_WAIT0();
        __syncthreads();
        if (kb + 1 < Ss / 64) {
            issueKV(kb + 1, s ^ 1);
            CP_COMMIT();
        }
        const uint32_t uKhi = sb + s * ASTG;
        const uint32_t uKlo = uKhi + ATL;
        const uint32_t uVhi = uKhi + 2 * ATL;

        // ---- S = Q K^T (3-MMA, pass-major: acc distance 8) ----
        float sc[8][4];
#pragma unroll
        for (int i = 0; i < 8; i++)
#pragma unroll
            for (int e = 0; e < 4; e++) sc[i][e] = 0.f;

#pragma unroll
        for (int j = 0; j < 4; j++) {
            // pass 1: qh · Khi
#pragma unroll
            for (int g = 0; g < 4; g++) {
                const uint32_t boff = (uint32_t)(g * 16) * AST + j * 32 + fragoff;
                uint32_t mh[4];
                ldmx4(mh, uKhi + boff);
                uint32_t b0[2] = {mh[0], mh[2]}, b1[2] = {mh[1], mh[3]};
                mma_f16(sc[2 * g + 0], qh[j], b0);
                mma_f16(sc[2 * g + 1], qh[j], b1);
            }
            // pass 2: qh · Klo
#pragma unroll
            for (int g = 0; g < 4; g++) {
                const uint32_t boff = (uint32_t)(g * 16) * AST + j * 32 + fragoff;
                uint32_t ml[4];
                ldmx4(ml, uKlo + boff);
                uint32_t b0[2] = {ml[0], ml[2]}, b1[2] = {ml[1], ml[3]};
                mma_f16(sc[2 * g + 0], qh[j], b0);
                mma_f16(sc[2 * g + 1], qh[j], b1);
            }
            // pass 3: ql · Khi (reload hi frags)
#pragma unroll
            for (int g = 0; g < 4; g++) {
                const uint32_t boff = (uint32_t)(g * 16) * AST + j * 32 + fragoff;
                uint32_t mh[4];
                ldmx4(mh, uKhi + boff);
                uint32_t b0[2] = {mh[0], mh[2]}, b1[2] = {mh[1], mh[3]};
                mma_f16(sc[2 * g + 0], ql[j], b0);
                mma_f16(sc[2 * g + 1], ql[j], b1);
            }
        }

        // ---- online softmax ----
        float mx0 = -1e30f, mx1 = -1e30f;
#pragma unroll
        for (int i = 0; i < 8; i++) {
            mx0 = fmaxf(mx0, fmaxf(sc[i][0], sc[i][1]));
            mx1 = fmaxf(mx1, fmaxf(sc[i][2], sc[i][3]));
        }
        mx0 = fmaxf(mx0, __shfl_xor_sync(0xffffffffu, mx0, 1));
        mx0 = fmaxf(mx0, __shfl_xor_sync(0xffffffffu, mx0, 2));
        mx1 = fmaxf(mx1, __shfl_xor_sync(0xffffffffu, mx1, 1));
        mx1 = fmaxf(mx1, __shfl_xor_sync(0xffffffffu, mx1, 2));
        const float mn0 = fmaxf(m0, mx0);
        const float mn1 = fmaxf(m1, mx1);
        const float c0 = __expf(m0 - mn0);
        const float c1 = __expf(m1 - mn1);
        float rs0 = 0.f, rs1 = 0.f;
#pragma unroll
        for (int i = 0; i < 8; i++) {
            sc[i][0] = __expf(sc[i][0] - mn0);
            sc[i][1] = __expf(sc[i][1] - mn0);
            sc[i][2] = __expf(sc[i][2] - mn1);
            sc[i][3] = __expf(sc[i][3] - mn1);
            rs0 += sc[i][0] + sc[i][1];
            rs1 += sc[i][2] + sc[i][3];
        }
        rs0 += __shfl_xor_sync(0xffffffffu, rs0, 1);
        rs0 += __shfl_xor_sync(0xffffffffu, rs0, 2);
        rs1 += __shfl_xor_sync(0xffffffffu, rs1, 1);
        rs1 += __shfl_xor_sync(0xffffffffu, rs1, 2);
        l0 = l0 * c0 + rs0;
        l1 = l1 * c1 + rs1;
        m0 = mn0;
        m1 = mn1;
#pragma unroll
        for (int i = 0; i < 8; i++) {
            o[i][0] *= c0; o[i][1] *= c0;
            o[i][2] *= c1; o[i][3] *= c1;
        }

        // ---- repack P (C-frag -> A-frag), hi/lo fp16 ----
        uint32_t ph[4][4], pl[4][4];
#pragma unroll
        for (int j = 0; j < 4; j++) {
            cvt_packh(sc[2 * j][0],     sc[2 * j][1],     ph[j][0], pl[j][0]);
            cvt_packh(sc[2 * j][2],     sc[2 * j][3],     ph[j][1], pl[j][1]);
            cvt_packh(sc[2 * j + 1][0], sc[2 * j + 1][1], ph[j][2], pl[j][2]);
            cvt_packh(sc[2 * j + 1][2], sc[2 * j + 1][3], ph[j][3], pl[j][3]);
        }

        // ---- O += P V (2-MMA, pass-major: acc distance 8) ----
#pragma unroll
        for (int j = 0; j < 4; j++) {
            // pass 1: ph · Vhi
#pragma unroll
            for (int g = 0; g < 4; g++) {
                const uint32_t voff = (uint32_t)(j * 16) * AST + g * 32 + fragoff;
                uint32_t mh[4];
                ldmx4t(mh, uVhi + voff);
                uint32_t b0[2] = {mh[0], mh[1]}, b1[2] = {mh[2], mh[3]};
                mma_f16(o[2 * g + 0], ph[j], b0);
                mma_f16(o[2 * g + 1], ph[j], b1);
            }
            // pass 2: pl · Vhi (reload frags)
#pragma unroll
            for (int g = 0; g < 4; g++) {
                const uint32_t voff = (uint32_t)(j * 16) * AST + g * 32 + fragoff;
                uint32_t mh[4];
                ldmx4t(mh, uVhi + voff);
                uint32_t b0[2] = {mh[0], mh[1]}, b1[2] = {mh[2], mh[3]};
                mma_f16(o[2 * g + 0], pl[j], b0);
                mma_f16(o[2 * g + 1], pl[j], b1);
            }
        }
    }

    // ---- epilogue: write fp16 hi/lo planes ----
    const float inv0 = 1.f / l0;
    const float inv1 = 1.f / l1;
    const int r0 = qt * 128 + warp * 16 + (lane >> 2);
    const size_t base0 = ((size_t)b * Ss + r0) * Dd + headoff + (lane & 3) * 2;
    const size_t base1 = base0 + (size_t)8 * Dd;
#pragma unroll
    for (int nt = 0; nt < 8; nt++) {
        uint32_t h0, l0u, h1, l1u;
        cvt_packh(o[nt][0] * inv0, o[nt][1] * inv0, h0, l0u);
        cvt_packh(o[nt][2] * inv1, o[nt][3] * inv1, h1, l1u);
        ((uint32_t*)ohi)[(base0 + nt * 8) / 2] = h0;
        ((uint32_t*)olo)[(base0 + nt * 8) / 2] = l0u;
        ((uint32_t*)ohi)[(base1 + nt * 8) / 2] = h1;
        ((uint32_t*)olo)[(base1 + nt * 8) / 2] = l1u;
    }
}

// ---------------------------------------------------------------------------
extern "C" void kernel_launch(void* const* d_in, const int* in_sizes, int n_in,
                              void* d_out, int out_size)
{
    (void)in_sizes; (void)n_in; (void)out_size;
    const float* x  = (const float*)d_in[0];
    const float* w1 = (const float*)d_in[1];
    const float* b1 = (const float*)d_in[2];
    const float* w2 = (const float*)d_in[3];
    const float* b2 = (const float*)d_in[4];
    float* out = (float*)d_out;

    __half *xhi, *xlo, *w1hi, *w1lo, *w2hi, *w2lo, *qhi, *qlo, *ahi, *alo;
    cudaGetSymbolAddress((void**)&xhi, g_xhi);
    cudaGetSymbolAddress((void**)&xlo, g_xlo);
    cudaGetSymbolAddress((void**)&w1hi, g_w1hi);
    cudaGetSymbolAddress((void**)&w1lo, g_w1lo);
    cudaGetSymbolAddress((void**)&w2hi, g_w2hi);
    cudaGetSymbolAddress((void**)&w2lo, g_w2lo);
    cudaGetSymbolAddress((void**)&qhi, g_qkvhi);
    cudaGetSymbolAddress((void**)&qlo, g_qkvlo);
    cudaGetSymbolAddress((void**)&ahi, g_ahi);
    cudaGetSymbolAddress((void**)&alo, g_alo);

    cudaFuncSetAttribute(gemm_hf<0>, cudaFuncAttributeMaxDynamicSharedMemorySize, GEMM_SMEM);
    cudaFuncSetAttribute(gemm_hf<1>, cudaFuncAttributeMaxDynamicSharedMemorySize, GEMM_SMEM);
    cudaFuncSetAttribute(flash2, cudaFuncAttributeMaxDynamicSharedMemorySize, ATTN_SMEM);

    // pre-convert
    split_f32<<<(MM * Dd / 2 + 255) / 256, 256>>>(x, xhi, xlo, MM * Dd / 2);
    transpose_split<<<dim3(N1 / 32, Dd / 64), 256>>>(w1, w1hi, w1lo, Dd, N1);
    transpose_split<<<dim3(Dd / 32, Dd / 64), 256>>>(w2, w2hi, w2lo, Dd, Dd);

    // 1) QKV projection -> fp16 planes (Q,K cols: 3-MMA; V cols: 2-MMA)
    gemm_hf<1><<<dim3(N1 / 128, MM / 128), 256, GEMM_SMEM>>>(
        xhi, xlo, w1hi, w1lo, b1, nullptr, qhi, qlo, MM, N1, Dd, 2 * Dd);
    // 2) attention -> fp16 planes
    flash2<<<dim3(Ss / 128, Bb * Hh), 256, ATTN_SMEM>>>(qhi, qlo, ahi, alo);
    // 3) output projection (2-MMA) -> fp32 out
    gemm_hf<0><<<dim3(Dd / 128, MM / 128), 256, GEMM_SMEM>>>(
        ahi, alo, w2hi, w2lo, b2, out, nullptr, nullptr, MM, Dd, Dd, 0);
}

// round 9
// speedup vs baseline: 1.3842x; 1.2774x over previous
#include <cuda_runtime.h>
#include <cuda_fp16.h>
#include <cstdint>

// Problem constants
#define Bb 4
#define Ss 2048
#define Dd 1024
#define Hh 16
#define DHd 64
#define MM (Bb * Ss)          // 8192
#define N1 (3 * Dd)           // 3072

// ---------------- global scratch (fp16 hi/lo planes) ----------------
__device__ __half g_xhi[(size_t)MM * Dd];
__device__ __half g_xlo[(size_t)MM * Dd];
__device__ __half g_w1hi[(size_t)N1 * Dd];    // [n][k]
__device__ __half g_w1lo[(size_t)N1 * Dd];
__device__ __half g_w2hi[(size_t)Dd * Dd];    // [n][k]
__device__ __half g_qkvhi[(size_t)MM * N1];
__device__ __half g_qkvlo[(size_t)MM * N1];   // lo only valid for Q,K cols
__device__ __half g_ahi[(size_t)MM * Dd];

// ---------------- helpers ----------------
__device__ __forceinline__ uint32_t s2u(const void* p) {
    uint32_t a;
    asm("{ .reg .u64 t; cvta.to.shared.u64 t, %1; cvt.u32.u64 %0, t; }" : "=r"(a) : "l"(p));
    return a;
}
__device__ __forceinline__ void cp16(uint32_t saddr, const void* gaddr) {
    asm volatile("cp.async.cg.shared.global [%0], [%1], 16;" :: "r"(saddr), "l"(gaddr));
}
#define CP_COMMIT() asm volatile("cp.async.commit_group;" ::: "memory")
#define CP_WAIT0()  asm volatile("cp.async.wait_group 0;" ::: "memory")

__device__ __forceinline__ void ldmx4(uint32_t* r, uint32_t addr) {
    asm volatile("ldmatrix.sync.aligned.m8n8.x4.shared.b16 {%0,%1,%2,%3}, [%4];"
        : "=r"(r[0]), "=r"(r[1]), "=r"(r[2]), "=r"(r[3]) : "r"(addr));
}
__device__ __forceinline__ void ldmx4t(uint32_t* r, uint32_t addr) {
    asm volatile("ldmatrix.sync.aligned.m8n8.x4.trans.shared.b16 {%0,%1,%2,%3}, [%4];"
        : "=r"(r[0]), "=r"(r[1]), "=r"(r[2]), "=r"(r[3]) : "r"(addr));
}
__device__ __forceinline__ void mma_f16(float* c, const uint32_t* a, const uint32_t* b) {
    asm volatile("mma.sync.aligned.m16n8k16.row.col.f32.f16.f16.f32 "
        "{%0,%1,%2,%3}, {%4,%5,%6,%7}, {%8,%9}, {%0,%1,%2,%3};"
        : "+f"(c[0]), "+f"(c[1]), "+f"(c[2]), "+f"(c[3])
        : "r"(a[0]), "r"(a[1]), "r"(a[2]), "r"(a[3]), "r"(b[0]), "r"(b[1]));
}
// fp32 pair -> packed fp16 hi pair + fp16 lo pair (hi = rn(f), lo = rn(f - hi))
__device__ __forceinline__ void cvt_packh(float f0, float f1, uint32_t& hi, uint32_t& lo) {
    __half h0 = __float2half_rn(f0);
    __half h1 = __float2half_rn(f1);
    __half l0 = __float2half_rn(f0 - __half2float(h0));
    __half l1 = __float2half_rn(f1 - __half2float(h1));
    hi = ((uint32_t)__half_as_ushort(h1) << 16) | (uint32_t)__half_as_ushort(h0);
    lo = ((uint32_t)__half_as_ushort(l1) << 16) | (uint32_t)__half_as_ushort(l0);
}
__device__ __forceinline__ uint32_t pack_h(float f0, float f1) {
    __half h0 = __float2half_rn(f0);
    __half h1 = __float2half_rn(f1);
    return ((uint32_t)__half_as_ushort(h1) << 16) | (uint32_t)__half_as_ushort(h0);
}

// ---------------- pre-convert kernels ----------------
__global__ void __launch_bounds__(256) split_f32(
    const float* __restrict__ src, __half* __restrict__ hi,
    __half* __restrict__ lo, int n2)
{
    int i = blockIdx.x * 256 + threadIdx.x;
    if (i >= n2) return;
    float2 v = *(const float2*)(src + 2 * i);
    uint32_t h, l;
    cvt_packh(v.x, v.y, h, l);
    ((uint32_t*)hi)[i] = h;
    ((uint32_t*)lo)[i] = l;
}

// W[K][N] fp32 -> Wt hi(/lo) [N][K] fp16
__global__ void __launch_bounds__(256) transpose_split(
    const float* __restrict__ W, __half* __restrict__ Whi,
    __half* __restrict__ Wlo, int K, int N, int write_lo)
{
    __shared__ float sm[64][33];
    const int tid = threadIdx.x;
    const int n0 = blockIdx.x * 32;
    const int k0 = blockIdx.y * 64;
#pragma unroll
    for (int p = 0; p < 8; p++) {
        const int k = p * 8 + (tid >> 5);
        const int n = tid & 31;
        sm[k][n] = W[(size_t)(k0 + k) * N + n0 + n];
    }
    __syncthreads();
#pragma unroll
    for (int p = 0; p < 4; p++) {
        const int n = p * 8 + (tid >> 5);
        const int kp = tid & 31;
        uint32_t h, l;
        cvt_packh(sm[2 * kp][n], sm[2 * kp + 1][n], h, l);
        const size_t idx = ((size_t)(n0 + n) * K + k0) / 2 + kp;
        ((uint32_t*)Whi)[idx] = h;
        if (write_lo) ((uint32_t*)Wlo)[idx] = l;
    }
}

// ---------------------------------------------------------------------------
// GEMM from fp16 planes. C = A @ B^T(+bias), A [M][K], B [N][K].
// 128x128 tile, BK=32, cp.async double-buffered, 8 warps (2m x 4n).
// Passes: ah·bh always; ah·bl when col0 < n3lim; al·bh when use_alo.
// EPI: 0 -> fp32 C, 1 -> fp16 hi(+lo when col0 < lo_lim) planes.
// ---------------------------------------------------------------------------
#define GST 80
#define GTILE (128 * GST)
#define GSTAGE (4 * GTILE)
#define GEMM_SMEM (2 * GSTAGE)

template<int EPI>
__global__ void __launch_bounds__(256, 2) gemm_hf(
    const __half* __restrict__ Ahi, const __half* __restrict__ Alo,
    const __half* __restrict__ Bhi, const __half* __restrict__ Blo,
    const float* __restrict__ bias, float* __restrict__ Cf,
    __half* __restrict__ Chi, __half* __restrict__ Clo,
    int M, int N, int K, int n3lim, int use_alo, int lo_lim)
{
    extern __shared__ char smem[];
    const int tid = threadIdx.x;
    const int lane = tid & 31;
    const int warp = tid >> 5;
    const int wm = warp >> 2;
    const int wn = warp & 3;
    const int row0 = blockIdx.y * 128;
    const int col0 = blockIdx.x * 128;
    const bool use3 = (col0 < n3lim);
    const bool ualo = (use_alo != 0);

    const int lrow = tid >> 1;
    const int lq = (tid & 1) * 2;

    auto issue = [&](int kc, int s) {
        char* stg = smem + s * GSTAGE;
        const uint32_t sA = s2u(stg) + (uint32_t)lrow * GST + lq * 16;
        const size_t gOffA = (size_t)(row0 + lrow) * K + kc * 32 + lq * 8;
        cp16(sA, Ahi + gOffA);
        cp16(sA + 16, Ahi + gOffA + 8);
        if (ualo) {
            cp16(sA + GTILE, Alo + gOffA);
            cp16(sA + GTILE + 16, Alo + gOffA + 8);
        }
        const size_t gOffB = (size_t)(col0 + lrow) * K + kc * 32 + lq * 8;
        cp16(sA + 2 * GTILE, Bhi + gOffB);
        cp16(sA + 2 * GTILE + 16, Bhi + gOffB + 8);
        if (use3) {
            cp16(sA + 3 * GTILE, Blo + gOffB);
            cp16(sA + 3 * GTILE + 16, Blo + gOffB + 8);
        }
    };

    float acc[4][4][4];
#pragma unroll
    for (int i = 0; i < 4; i++)
#pragma unroll
        for (int j = 0; j < 4; j++)
#pragma unroll
            for (int e = 0; e < 4; e++) acc[i][j][e] = 0.f;

    const uint32_t fragoff = (uint32_t)(lane & 15) * GST + (uint32_t)(lane >> 4) * 16;

    issue(0, 0);
    CP_COMMIT();

    const int nch = K / 32;
    for (int kc = 0; kc < nch; kc++) {
        const int s = kc & 1;
        CP_WAIT0();
        __syncthreads();
        if (kc + 1 < nch) {
            issue(kc + 1, s ^ 1);
            CP_COMMIT();
        }
        char* stg = smem + s * GSTAGE;
        const uint32_t uAhi = s2u(stg);
        const uint32_t uAlo = uAhi + GTILE;
        const uint32_t uBhi = uAhi + 2 * GTILE;
        const uint32_t uBlo = uAhi + 3 * GTILE;

#pragma unroll
        for (int ks = 0; ks < 2; ks++) {
            const uint32_t kb = (uint32_t)ks * 32;
            uint32_t bh[4][2], bl[4][2];
#pragma unroll
            for (int ntp = 0; ntp < 2; ntp++) {
                const uint32_t boff = (uint32_t)(wn * 32 + ntp * 16) * GST + kb + fragoff;
                uint32_t m[4];
                ldmx4(m, uBhi + boff);
                bh[ntp * 2 + 0][0] = m[0]; bh[ntp * 2 + 1][0] = m[1];
                bh[ntp * 2 + 0][1] = m[2]; bh[ntp * 2 + 1][1] = m[3];
                if (use3) {
                    ldmx4(m, uBlo + boff);
                    bl[ntp * 2 + 0][0] = m[0]; bl[ntp * 2 + 1][0] = m[1];
                    bl[ntp * 2 + 0][1] = m[2]; bl[ntp * 2 + 1][1] = m[3];
                }
            }
            uint32_t ah[4][4];
#pragma unroll
            for (int mt = 0; mt < 4; mt++) {
                const uint32_t aoff = (uint32_t)(wm * 64 + mt * 16) * GST + kb + fragoff;
                ldmx4(ah[mt], uAhi + aoff);
            }
            // PASS 1: ah·bh
#pragma unroll
            for (int mt = 0; mt < 4; mt++)
#pragma unroll
                for (int nt = 0; nt < 4; nt++)
                    mma_f16(acc[mt][nt], ah[mt], bh[nt]);
            // PASS 2: ah·bl
            if (use3) {
#pragma unroll
                for (int mt = 0; mt < 4; mt++)
#pragma unroll
                    for (int nt = 0; nt < 4; nt++)
                        mma_f16(acc[mt][nt], ah[mt], bl[nt]);
            }
            // PASS 3: al·bh
            if (ualo) {
#pragma unroll
                for (int mt = 0; mt < 4; mt++) {
                    const uint32_t aoff = (uint32_t)(wm * 64 + mt * 16) * GST + kb + fragoff;
                    uint32_t al[4];
                    ldmx4(al, uAlo + aoff);
#pragma unroll
                    for (int nt = 0; nt < 4; nt++)
                        mma_f16(acc[mt][nt], al, bh[nt]);
                }
            }
        }
    }

    // epilogue
    const bool wlo = (col0 < lo_lim);
#pragma unroll
    for (int mt = 0; mt < 4; mt++) {
        const int r = row0 + wm * 64 + mt * 16 + (lane >> 2);
#pragma unroll
        for (int nt = 0; nt < 4; nt++) {
            const int c = col0 + wn * 32 + nt * 8 + (lane & 3) * 2;
            const float bx = bias[c];
            const float by = bias[c + 1];
            const float f0 = acc[mt][nt][0] + bx;
            const float f1 = acc[mt][nt][1] + by;
            const float f2 = acc[mt][nt][2] + bx;
            const float f3 = acc[mt][nt][3] + by;
            if (EPI == 0) {
                *(float2*)(Cf + (size_t)r * N + c) = make_float2(f0, f1);
                *(float2*)(Cf + (size_t)(r + 8) * N + c) = make_float2(f2, f3);
            } else {
                uint32_t h0, l0, h1, l1;
                cvt_packh(f0, f1, h0, l0);
                cvt_packh(f2, f3, h1, l1);
                const size_t i0 = ((size_t)r * N + c) / 2;
                const size_t i1 = ((size_t)(r + 8) * N + c) / 2;
                ((uint32_t*)Chi)[i0] = h0;
                ((uint32_t*)Chi)[i1] = h1;
                if (wlo) {
                    ((uint32_t*)Clo)[i0] = l0;
                    ((uint32_t*)Clo)[i1] = l1;
                }
            }
        }
    }
}

// ---------------------------------------------------------------------------
// Flash attention from fp16 qkv planes. QK: 3-MMA (pass-major, acc distance 8).
// PV: 1-MMA (P hi only, V hi only). Output: hi plane only.
// ---------------------------------------------------------------------------
#define AST 144
#define ATL (64 * AST)
#define ASTG (3 * ATL)              // Khi,Klo,Vhi = 27648
#define ATTN_SMEM (ASTG + 2 * 128 * AST)   // 64512

__global__ void __launch_bounds__(256) flash2(
    const __half* __restrict__ qhi, const __half* __restrict__ qlo,
    __half* __restrict__ ohi)
{
    extern __shared__ char smem[];
    const int tid = threadIdx.x;
    const int lane = tid & 31;
    const int warp = tid >> 5;
    const int qt = blockIdx.x;
    const int bh = blockIdx.y;
    const int b = bh >> 4;
    const int h = bh & 15;

    const uint32_t sb = s2u(smem);
    const uint32_t fragoff = (uint32_t)(lane & 15) * AST + (uint32_t)(lane >> 4) * 16;
    const size_t headoff = (size_t)h * DHd;

    const int krow = tid >> 2;
    const int kcc = (tid & 3) * 2;
    auto issueKV = [&](int kb, int s) {
        const uint32_t sB = sb + s * ASTG + (uint32_t)krow * AST + kcc * 16;
        const size_t g = ((size_t)b * Ss + kb * 64 + krow) * N1 + headoff + kcc * 8;
        cp16(sB,                 qhi + g + Dd);       // K hi
        cp16(sB + 16,            qhi + g + Dd + 8);
        cp16(sB + ATL,           qlo + g + Dd);       // K lo
        cp16(sB + ATL + 16,      qlo + g + Dd + 8);
        cp16(sB + 2 * ATL,       qhi + g + 2 * Dd);   // V hi
        cp16(sB + 2 * ATL + 16,  qhi + g + 2 * Dd + 8);
    };

    // preload: K/V block0 -> stage0; Q -> region above stage0 (overlaps stage1,
    // safe: Q is consumed into registers before stage1 is first written)
    issueKV(0, 0);
    CP_COMMIT();
    {
        const int qrow = tid >> 1;
        const int q4 = (tid & 1) * 4;
        const uint32_t sQh = sb + ASTG + (uint32_t)qrow * AST + q4 * 16;
        const uint32_t sQl = sQh + 128 * AST;
        const size_t g = ((size_t)b * Ss + qt * 128 + qrow) * N1 + headoff + q4 * 8;
#pragma unroll
        for (int i = 0; i < 4; i++) {
            cp16(sQh + i * 16, qhi + g + i * 8);
            cp16(sQl + i * 16, qlo + g + i * 8);
        }
    }
    CP_COMMIT();
    CP_WAIT0();
    __syncthreads();

    // Q fragments (extracted before stage1 is ever written)
    uint32_t qh[4][4], ql[4][4];
    {
        const uint32_t uQh = sb + ASTG;
        const uint32_t uQl = uQh + 128 * AST;
#pragma unroll
        for (int j = 0; j < 4; j++) {
            const uint32_t aoff = (uint32_t)(warp * 16) * AST + j * 32 + fragoff;
            ldmx4(qh[j], uQh + aoff);
            ldmx4(ql[j], uQl + aoff);
        }
    }

    float o[8][4];
    float m0 = -1e30f, m1 = -1e30f, l0 = 0.f, l1 = 0.f;
#pragma unroll
    for (int i = 0; i < 8; i++)
#pragma unroll
        for (int e = 0; e < 4; e++) o[i][e] = 0.f;

    for (int kb = 0; kb < Ss / 64; kb++) {
        const int s = kb & 1;
        if (kb > 0) CP_WAIT0();
        __syncthreads();
        if (kb + 1 < Ss / 64) {
            issueKV(kb + 1, s ^ 1);
            CP_COMMIT();
        }
        const uint32_t uKhi = sb + s * ASTG;
        const uint32_t uKlo = uKhi + ATL;
        const uint32_t uVhi = uKhi + 2 * ATL;

        // ---- S = Q K^T (3-MMA, pass-major: acc distance 8) ----
        float sc[8][4];
#pragma unroll
        for (int i = 0; i < 8; i++)
#pragma unroll
            for (int e = 0; e < 4; e++) sc[i][e] = 0.f;

#pragma unroll
        for (int j = 0; j < 4; j++) {
            // pass 1: qh · Khi
#pragma unroll
            for (int g = 0; g < 4; g++) {
                const uint32_t boff = (uint32_t)(g * 16) * AST + j * 32 + fragoff;
                uint32_t mh[4];
                ldmx4(mh, uKhi + boff);
                uint32_t b0[2] = {mh[0], mh[2]}, b1[2] = {mh[1], mh[3]};
                mma_f16(sc[2 * g + 0], qh[j], b0);
                mma_f16(sc[2 * g + 1], qh[j], b1);
            }
            // pass 2: qh · Klo
#pragma unroll
            for (int g = 0; g < 4; g++) {
                const uint32_t boff = (uint32_t)(g * 16) * AST + j * 32 + fragoff;
                uint32_t ml[4];
                ldmx4(ml, uKlo + boff);
                uint32_t b0[2] = {ml[0], ml[2]}, b1[2] = {ml[1], ml[3]};
                mma_f16(sc[2 * g + 0], qh[j], b0);
                mma_f16(sc[2 * g + 1], qh[j], b1);
            }
            // pass 3: ql · Khi (reload hi frags)
#pragma unroll
            for (int g = 0; g < 4; g++) {
                const uint32_t boff = (uint32_t)(g * 16) * AST + j * 32 + fragoff;
                uint32_t mh[4];
                ldmx4(mh, uKhi + boff);
                uint32_t b0[2] = {mh[0], mh[2]}, b1[2] = {mh[1], mh[3]};
                mma_f16(sc[2 * g + 0], ql[j], b0);
                mma_f16(sc[2 * g + 1], ql[j], b1);
            }
        }

        // ---- online softmax ----
        float mx0 = -1e30f, mx1 = -1e30f;
#pragma unroll
        for (int i = 0; i < 8; i++) {
            mx0 = fmaxf(mx0, fmaxf(sc[i][0], sc[i][1]));
            mx1 = fmaxf(mx1, fmaxf(sc[i][2], sc[i][3]));
        }
        mx0 = fmaxf(mx0, __shfl_xor_sync(0xffffffffu, mx0, 1));
        mx0 = fmaxf(mx0, __shfl_xor_sync(0xffffffffu, mx0, 2));
        mx1 = fmaxf(mx1, __shfl_xor_sync(0xffffffffu, mx1, 1));
        mx1 = fmaxf(mx1, __shfl_xor_sync(0xffffffffu, mx1, 2));
        const float mn0 = fmaxf(m0, mx0);
        const float mn1 = fmaxf(m1, mx1);
        const float c0 = __expf(m0 - mn0);
        const float c1 = __expf(m1 - mn1);
        float rs0 = 0.f, rs1 = 0.f;
#pragma unroll
        for (int i = 0; i < 8; i++) {
            sc[i][0] = __expf(sc[i][0] - mn0);
            sc[i][1] = __expf(sc[i][1] - mn0);
            sc[i][2] = __expf(sc[i][2] - mn1);
            sc[i][3] = __expf(sc[i][3] - mn1);
            rs0 += sc[i][0] + sc[i][1];
            rs1 += sc[i][2] + sc[i][3];
        }
        rs0 += __shfl_xor_sync(0xffffffffu, rs0, 1);
        rs0 += __shfl_xor_sync(0xffffffffu, rs0, 2);
        rs1 += __shfl_xor_sync(0xffffffffu, rs1, 1);
        rs1 += __shfl_xor_sync(0xffffffffu, rs1, 2);
        l0 = l0 * c0 + rs0;
        l1 = l1 * c1 + rs1;
        m0 = mn0;
        m1 = mn1;
#pragma unroll
        for (int i = 0; i < 8; i++) {
            o[i][0] *= c0; o[i][1] *= c0;
            o[i][2] *= c1; o[i][3] *= c1;
        }

        // ---- repack P hi only (C-frag -> A-frag) ----
        uint32_t ph[4][4];
#pragma unroll
        for (int j = 0; j < 4; j++) {
            ph[j][0] = pack_h(sc[2 * j][0],     sc[2 * j][1]);
            ph[j][1] = pack_h(sc[2 * j][2],     sc[2 * j][3]);
            ph[j][2] = pack_h(sc[2 * j + 1][0], sc[2 * j + 1][1]);
            ph[j][3] = pack_h(sc[2 * j + 1][2], sc[2 * j + 1][3]);
        }

        // ---- O += P V (1-MMA, acc distance 8 across g) ----
#pragma unroll
        for (int j = 0; j < 4; j++) {
#pragma unroll
            for (int g = 0; g < 4; g++) {
                const uint32_t voff = (uint32_t)(j * 16) * AST + g * 32 + fragoff;
                uint32_t mh[4];
                ldmx4t(mh, uVhi + voff);
                uint32_t b0[2] = {mh[0], mh[1]}, b1[2] = {mh[2], mh[3]};
                mma_f16(o[2 * g + 0], ph[j], b0);
                mma_f16(o[2 * g + 1], ph[j], b1);
            }
        }
    }

    // ---- epilogue: write hi plane only ----
    const float inv0 = 1.f / l0;
    const float inv1 = 1.f / l1;
    const int r0 = qt * 128 + warp * 16 + (lane >> 2);
    const size_t base0 = ((size_t)b * Ss + r0) * Dd + headoff + (lane & 3) * 2;
    const size_t base1 = base0 + (size_t)8 * Dd;
#pragma unroll
    for (int nt = 0; nt < 8; nt++) {
        ((uint32_t*)ohi)[(base0 + nt * 8) / 2] = pack_h(o[nt][0] * inv0, o[nt][1] * inv0);
        ((uint32_t*)ohi)[(base1 + nt * 8) / 2] = pack_h(o[nt][2] * inv1, o[nt][3] * inv1);
    }
}

// ---------------------------------------------------------------------------
extern "C" void kernel_launch(void* const* d_in, const int* in_sizes, int n_in,
                              void* d_out, int out_size)
{
    (void)in_sizes; (void)n_in; (void)out_size;
    const float* x  = (const float*)d_in[0];
    const float* w1 = (const float*)d_in[1];
    const float* b1 = (const float*)d_in[2];
    const float* w2 = (const float*)d_in[3];
    const float* b2 = (const float*)d_in[4];
    float* out = (float*)d_out;

    __half *xhi, *xlo, *w1hi, *w1lo, *w2hi, *qhi, *qlo, *ahi;
    cudaGetSymbolAddress((void**)&xhi, g_xhi);
    cudaGetSymbolAddress((void**)&xlo, g_xlo);
    cudaGetSymbolAddress((void**)&w1hi, g_w1hi);
    cudaGetSymbolAddress((void**)&w1lo, g_w1lo);
    cudaGetSymbolAddress((void**)&w2hi, g_w2hi);
    cudaGetSymbolAddress((void**)&qhi, g_qkvhi);
    cudaGetSymbolAddress((void**)&qlo, g_qkvlo);
    cudaGetSymbolAddress((void**)&ahi, g_ahi);

    cudaFuncSetAttribute(gemm_hf<0>, cudaFuncAttributeMaxDynamicSharedMemorySize, GEMM_SMEM);
    cudaFuncSetAttribute(gemm_hf<1>, cudaFuncAttributeMaxDynamicSharedMemorySize, GEMM_SMEM);
    cudaFuncSetAttribute(flash2, cudaFuncAttributeMaxDynamicSharedMemorySize, ATTN_SMEM);

    // pre-convert
    split_f32<<<(MM * Dd / 2 + 255) / 256, 256>>>(x, xhi, xlo, MM * Dd / 2);
    transpose_split<<<dim3(N1 / 32, Dd / 64), 256>>>(w1, w1hi, w1lo, Dd, N1, 1);
    transpose_split<<<dim3(Dd / 32, Dd / 64), 256>>>(w2, w2hi, nullptr, Dd, Dd, 0);

    // 1) QKV projection -> fp16 planes (Q,K: 3-MMA + lo stores; V: 2-MMA, hi only)
    gemm_hf<1><<<dim3(N1 / 128, MM / 128), 256, GEMM_SMEM>>>(
        xhi, xlo, w1hi, w1lo, b1, nullptr, qhi, qlo, MM, N1, Dd,
        /*n3lim=*/2 * Dd, /*use_alo=*/1, /*lo_lim=*/2 * Dd);
    // 2) attention -> a hi plane (QK 3-MMA, PV 1-MMA)
    flash2<<<dim3(Ss / 128, Bb * Hh), 256, ATTN_SMEM>>>(qhi, qlo, ahi);
    // 3) output projection (1-MMA pure fp16) -> fp32 out
    gemm_hf<0><<<dim3(Dd / 128, MM / 128), 256, GEMM_SMEM>>>(
        ahi, nullptr, w2hi, nullptr, b2, out, nullptr, nullptr, MM, Dd, Dd,
        /*n3lim=*/0, /*use_alo=*/0, /*lo_lim=*/0);
}

// round 11
// speedup vs baseline: 1.4371x; 1.0382x over previous
#include <cuda_runtime.h>
#include <cuda_fp16.h>
#include <cstdint>

// Problem constants
#define Bb 4
#define Ss 2048
#define Dd 1024
#define Hh 16
#define DHd 64
#define MM (Bb * Ss)          // 8192
#define N1 (3 * Dd)           // 3072

// ---------------- global scratch (fp16 hi/lo planes) ----------------
__device__ __half g_xhi[(size_t)MM * Dd];
__device__ __half g_xlo[(size_t)MM * Dd];
__device__ __half g_w1hi[(size_t)N1 * Dd];    // [n][k]
__device__ __half g_w1lo[(size_t)N1 * Dd];
__device__ __half g_w2hi[(size_t)Dd * Dd];    // [n][k]
__device__ __half g_qkvhi[(size_t)MM * N1];
__device__ __half g_qkvlo[(size_t)MM * N1];   // lo valid for Q,K cols
__device__ __half g_ahi[(size_t)MM * Dd];

// ---------------- helpers ----------------
__device__ __forceinline__ uint32_t s2u(const void* p) {
    uint32_t a;
    asm("{ .reg .u64 t; cvta.to.shared.u64 t, %1; cvt.u32.u64 %0, t; }" : "=r"(a) : "l"(p));
    return a;
}
__device__ __forceinline__ void cp16(uint32_t saddr, const void* gaddr) {
    asm volatile("cp.async.cg.shared.global [%0], [%1], 16;" :: "r"(saddr), "l"(gaddr));
}
#define CP_COMMIT() asm volatile("cp.async.commit_group;" ::: "memory")
#define CP_WAIT0()  asm volatile("cp.async.wait_group 0;" ::: "memory")

__device__ __forceinline__ void ldmx4(uint32_t* r, uint32_t addr) {
    asm volatile("ldmatrix.sync.aligned.m8n8.x4.shared.b16 {%0,%1,%2,%3}, [%4];"
        : "=r"(r[0]), "=r"(r[1]), "=r"(r[2]), "=r"(r[3]) : "r"(addr));
}
__device__ __forceinline__ void ldmx4t(uint32_t* r, uint32_t addr) {
    asm volatile("ldmatrix.sync.aligned.m8n8.x4.trans.shared.b16 {%0,%1,%2,%3}, [%4];"
        : "=r"(r[0]), "=r"(r[1]), "=r"(r[2]), "=r"(r[3]) : "r"(addr));
}
__device__ __forceinline__ void mma_f16(float* c, const uint32_t* a, const uint32_t* b) {
    asm volatile("mma.sync.aligned.m16n8k16.row.col.f32.f16.f16.f32 "
        "{%0,%1,%2,%3}, {%4,%5,%6,%7}, {%8,%9}, {%0,%1,%2,%3};"
        : "+f"(c[0]), "+f"(c[1]), "+f"(c[2]), "+f"(c[3])
        : "r"(a[0]), "r"(a[1]), "r"(a[2]), "r"(a[3]), "r"(b[0]), "r"(b[1]));
}
// fp32 pair -> packed fp16 hi pair + fp16 lo pair (hi = rn(f), lo = rn(f - hi))
__device__ __forceinline__ void cvt_packh(float f0, float f1, uint32_t& hi, uint32_t& lo) {
    __half h0 = __float2half_rn(f0);
    __half h1 = __float2half_rn(f1);
    __half l0 = __float2half_rn(f0 - __half2float(h0));
    __half l1 = __float2half_rn(f1 - __half2float(h1));
    hi = ((uint32_t)__half_as_ushort(h1) << 16) | (uint32_t)__half_as_ushort(h0);
    lo = ((uint32_t)__half_as_ushort(l1) << 16) | (uint32_t)__half_as_ushort(l0);
}
__device__ __forceinline__ uint32_t pack_h(float f0, float f1) {
    __half h0 = __float2half_rn(f0);
    __half h1 = __float2half_rn(f1);
    return ((uint32_t)__half_as_ushort(h1) << 16) | (uint32_t)__half_as_ushort(h0);
}

// ---------------- pre-convert kernels ----------------
__global__ void __launch_bounds__(256) split_f32(
    const float* __restrict__ src, __half* __restrict__ hi,
    __half* __restrict__ lo, int n2)
{
    int i = blockIdx.x * 256 + threadIdx.x;
    if (i >= n2) return;
    float2 v = *(const float2*)(src + 2 * i);
    uint32_t h, l;
    cvt_packh(v.x, v.y, h, l);
    ((uint32_t*)hi)[i] = h;
    ((uint32_t*)lo)[i] = l;
}

// W[K][N] fp32 -> Wt hi(/lo) [N][K] fp16
__global__ void __launch_bounds__(256) transpose_split(
    const float* __restrict__ W, __half* __restrict__ Whi,
    __half* __restrict__ Wlo, int K, int N, int write_lo)
{
    __shared__ float sm[64][33];
    const int tid = threadIdx.x;
    const int n0 = blockIdx.x * 32;
    const int k0 = blockIdx.y * 64;
#pragma unroll
    for (int p = 0; p < 8; p++) {
        const int k = p * 8 + (tid >> 5);
        const int n = tid & 31;
        sm[k][n] = W[(size_t)(k0 + k) * N + n0 + n];
    }
    __syncthreads();
#pragma unroll
    for (int p = 0; p < 4; p++) {
        const int n = p * 8 + (tid >> 5);
        const int kp = tid & 31;
        uint32_t h, l;
        cvt_packh(sm[2 * kp][n], sm[2 * kp + 1][n], h, l);
        const size_t idx = ((size_t)(n0 + n) * K + k0) / 2 + kp;
        ((uint32_t*)Whi)[idx] = h;
        if (write_lo) ((uint32_t*)Wlo)[idx] = l;
    }
}

// ---------------------------------------------------------------------------
// GEMM from fp16 planes. C = A @ B^T(+bias), A [M][K], B [N][K].
// 128x128 tile, BK=32, cp.async double-buffered, 8 warps (2m x 4n).
// Column-range-configurable passes:
//   ah·bh always; ah·bl when col0 < n3lim; al·bh when col0 in [alo_lo, alo_hi).
// EPI: 0 -> fp32 C, 1 -> fp16 hi plane (+lo when col0 in [wlo_lo, wlo_hi)).
// ---------------------------------------------------------------------------
#define GST 80
#define GTILE (128 * GST)
#define GSTAGE (4 * GTILE)
#define GEMM_SMEM (2 * GSTAGE)

template<int EPI>
__global__ void __launch_bounds__(256, 2) gemm_hf(
    const __half* __restrict__ Ahi, const __half* __restrict__ Alo,
    const __half* __restrict__ Bhi, const __half* __restrict__ Blo,
    const float* __restrict__ bias, float* __restrict__ Cf,
    __half* __restrict__ Chi, __half* __restrict__ Clo,
    int M, int N, int K, int n3lim, int alo_lo, int alo_hi,
    int wlo_lo, int wlo_hi)
{
    extern __shared__ char smem[];
    const int tid = threadIdx.x;
    const int lane = tid & 31;
    const int warp = tid >> 5;
    const int wm = warp >> 2;
    const int wn = warp & 3;
    const int row0 = blockIdx.y * 128;
    const int col0 = blockIdx.x * 128;
    const bool use3 = (col0 < n3lim);
    const bool ualo = (col0 >= alo_lo) && (col0 < alo_hi);

    const int lrow = tid >> 1;
    const int lq = (tid & 1) * 2;

    auto issue = [&](int kc, int s) {
        char* stg = smem + s * GSTAGE;
        const uint32_t sA = s2u(stg) + (uint32_t)lrow * GST + lq * 16;
        const size_t gOffA = (size_t)(row0 + lrow) * K + kc * 32 + lq * 8;
        cp16(sA, Ahi + gOffA);
        cp16(sA + 16, Ahi + gOffA + 8);
        if (ualo) {
            cp16(sA + GTILE, Alo + gOffA);
            cp16(sA + GTILE + 16, Alo + gOffA + 8);
        }
        const size_t gOffB = (size_t)(col0 + lrow) * K + kc * 32 + lq * 8;
        cp16(sA + 2 * GTILE, Bhi + gOffB);
        cp16(sA + 2 * GTILE + 16, Bhi + gOffB + 8);
        if (use3) {
            cp16(sA + 3 * GTILE, Blo + gOffB);
            cp16(sA + 3 * GTILE + 16, Blo + gOffB + 8);
        }
    };

    float acc[4][4][4];
#pragma unroll
    for (int i = 0; i < 4; i++)
#pragma unroll
        for (int j = 0; j < 4; j++)
#pragma unroll
            for (int e = 0; e < 4; e++) acc[i][j][e] = 0.f;

    const uint32_t fragoff = (uint32_t)(lane & 15) * GST + (uint32_t)(lane >> 4) * 16;

    issue(0, 0);
    CP_COMMIT();

    const int nch = K / 32;
    for (int kc = 0; kc < nch; kc++) {
        const int s = kc & 1;
        CP_WAIT0();
        __syncthreads();
        if (kc + 1 < nch) {
            issue(kc + 1, s ^ 1);
            CP_COMMIT();
        }
        char* stg = smem + s * GSTAGE;
        const uint32_t uAhi = s2u(stg);
        const uint32_t uAlo = uAhi + GTILE;
        const uint32_t uBhi = uAhi + 2 * GTILE;
        const uint32_t uBlo = uAhi + 3 * GTILE;

#pragma unroll
        for (int ks = 0; ks < 2; ks++) {
            const uint32_t kb = (uint32_t)ks * 32;
            uint32_t bh[4][2], bl[4][2];
#pragma unroll
            for (int ntp = 0; ntp < 2; ntp++) {
                const uint32_t boff = (uint32_t)(wn * 32 + ntp * 16) * GST + kb + fragoff;
                uint32_t m[4];
                ldmx4(m, uBhi + boff);
                bh[ntp * 2 + 0][0] = m[0]; bh[ntp * 2 + 1][0] = m[1];
                bh[ntp * 2 + 0][1] = m[2]; bh[ntp * 2 + 1][1] = m[3];
                if (use3) {
                    ldmx4(m, uBlo + boff);
                    bl[ntp * 2 + 0][0] = m[0]; bl[ntp * 2 + 1][0] = m[1];
                    bl[ntp * 2 + 0][1] = m[2]; bl[ntp * 2 + 1][1] = m[3];
                }
            }
            uint32_t ah[4][4];
#pragma unroll
            for (int mt = 0; mt < 4; mt++) {
                const uint32_t aoff = (uint32_t)(wm * 64 + mt * 16) * GST + kb + fragoff;
                ldmx4(ah[mt], uAhi + aoff);
            }
            // PASS 1: ah·bh
#pragma unroll
            for (int mt = 0; mt < 4; mt++)
#pragma unroll
                for (int nt = 0; nt < 4; nt++)
                    mma_f16(acc[mt][nt], ah[mt], bh[nt]);
            // PASS 2: ah·bl
            if (use3) {
#pragma unroll
                for (int mt = 0; mt < 4; mt++)
#pragma unroll
                    for (int nt = 0; nt < 4; nt++)
                        mma_f16(acc[mt][nt], ah[mt], bl[nt]);
            }
            // PASS 3: al·bh
            if (ualo) {
#pragma unroll
                for (int mt = 0; mt < 4; mt++) {
                    const uint32_t aoff = (uint32_t)(wm * 64 + mt * 16) * GST + kb + fragoff;
                    uint32_t al[4];
                    ldmx4(al, uAlo + aoff);
#pragma unroll
                    for (int nt = 0; nt < 4; nt++)
                        mma_f16(acc[mt][nt], al, bh[nt]);
                }
            }
        }
    }

    // epilogue
    const bool wlo = (col0 >= wlo_lo) && (col0 < wlo_hi);
#pragma unroll
    for (int mt = 0; mt < 4; mt++) {
        const int r = row0 + wm * 64 + mt * 16 + (lane >> 2);
#pragma unroll
        for (int nt = 0; nt < 4; nt++) {
            const int c = col0 + wn * 32 + nt * 8 + (lane & 3) * 2;
            const float bx = bias[c];
            const float by = bias[c + 1];
            const float f0 = acc[mt][nt][0] + bx;
            const float f1 = acc[mt][nt][1] + by;
            const float f2 = acc[mt][nt][2] + bx;
            const float f3 = acc[mt][nt][3] + by;
            if (EPI == 0) {
                *(float2*)(Cf + (size_t)r * N + c) = make_float2(f0, f1);
                *(float2*)(Cf + (size_t)(r + 8) * N + c) = make_float2(f2, f3);
            } else {
                uint32_t h0, l0, h1, l1;
                cvt_packh(f0, f1, h0, l0);
                cvt_packh(f2, f3, h1, l1);
                const size_t i0 = ((size_t)r * N + c) / 2;
                const size_t i1 = ((size_t)(r + 8) * N + c) / 2;
                ((uint32_t*)Chi)[i0] = h0;
                ((uint32_t*)Chi)[i1] = h1;
                if (wlo) {
                    ((uint32_t*)Clo)[i0] = l0;
                    ((uint32_t*)Clo)[i1] = l1;
                }
            }
        }
    }
}

// ---------------------------------------------------------------------------
// Flash attention from fp16 qkv planes.
// QK: 3-MMA (qh·Khi + qh·Klo + ql·Khi) — score path needs full precision.
// PV: 1-MMA (P hi, V hi). Output: hi plane only.
// ---------------------------------------------------------------------------
#define AST 144
#define ATL (64 * AST)
#define ASTG (3 * ATL)              // Khi,Klo,Vhi = 27648
#define ATTN_SMEM (ASTG + 2 * 128 * AST)   // 64512 (Q hi+lo staging overlaps stage1)

__global__ void __launch_bounds__(256) flash2(
    const __half* __restrict__ qhi, const __half* __restrict__ qlo,
    __half* __restrict__ ohi)
{
    extern __shared__ char smem[];
    const int tid = threadIdx.x;
    const int lane = tid & 31;
    const int warp = tid >> 5;
    const int qt = blockIdx.x;
    const int bh = blockIdx.y;
    const int b = bh >> 4;
    const int h = bh & 15;

    const uint32_t sb = s2u(smem);
    const uint32_t fragoff = (uint32_t)(lane & 15) * AST + (uint32_t)(lane >> 4) * 16;
    const size_t headoff = (size_t)h * DHd;

    const int krow = tid >> 2;
    const int kcc = (tid & 3) * 2;
    auto issueKV = [&](int kb, int s) {
        const uint32_t sB = sb + s * ASTG + (uint32_t)krow * AST + kcc * 16;
        const size_t g = ((size_t)b * Ss + kb * 64 + krow) * N1 + headoff + kcc * 8;
        cp16(sB,                 qhi + g + Dd);       // K hi
        cp16(sB + 16,            qhi + g + Dd + 8);
        cp16(sB + ATL,           qlo + g + Dd);       // K lo
        cp16(sB + ATL + 16,      qlo + g + Dd + 8);
        cp16(sB + 2 * ATL,       qhi + g + 2 * Dd);   // V hi
        cp16(sB + 2 * ATL + 16,  qhi + g + 2 * Dd + 8);
    };

    // preload: K/V block0 -> stage0; Q hi+lo -> region above stage0 (overlaps
    // stage1; safe: Q is consumed into registers before stage1 is written)
    issueKV(0, 0);
    CP_COMMIT();
    {
        const int qrow = tid >> 1;
        const int q4 = (tid & 1) * 4;
        const uint32_t sQh = sb + ASTG + (uint32_t)qrow * AST + q4 * 16;
        const uint32_t sQl = sQh + 128 * AST;
        const size_t g = ((size_t)b * Ss + qt * 128 + qrow) * N1 + headoff + q4 * 8;
#pragma unroll
        for (int i = 0; i < 4; i++) {
            cp16(sQh + i * 16, qhi + g + i * 8);
            cp16(sQl + i * 16, qlo + g + i * 8);
        }
    }
    CP_COMMIT();
    CP_WAIT0();
    __syncthreads();

    // Q fragments (extracted before stage1 is ever written)
    uint32_t qh[4][4], ql[4][4];
    {
        const uint32_t uQh = sb + ASTG;
        const uint32_t uQl = uQh + 128 * AST;
#pragma unroll
        for (int j = 0; j < 4; j++) {
            const uint32_t aoff = (uint32_t)(warp * 16) * AST + j * 32 + fragoff;
            ldmx4(qh[j], uQh + aoff);
            ldmx4(ql[j], uQl + aoff);
        }
    }

    float o[8][4];
    float m0 = -1e30f, m1 = -1e30f, l0 = 0.f, l1 = 0.f;
#pragma unroll
    for (int i = 0; i < 8; i++)
#pragma unroll
        for (int e = 0; e < 4; e++) o[i][e] = 0.f;

    for (int kb = 0; kb < Ss / 64; kb++) {
        const int s = kb & 1;
        if (kb > 0) CP_WAIT0();
        __syncthreads();
        if (kb + 1 < Ss / 64) {
            issueKV(kb + 1, s ^ 1);
            CP_COMMIT();
        }
        const uint32_t uKhi = sb + s * ASTG;
        const uint32_t uKlo = uKhi + ATL;
        const uint32_t uVhi = uKhi + 2 * ATL;

        // ---- S = Q K^T (3-MMA, pass-major: acc distance 8) ----
        float sc[8][4];
#pragma unroll
        for (int i = 0; i < 8; i++)
#pragma unroll
            for (int e = 0; e < 4; e++) sc[i][e] = 0.f;

#pragma unroll
        for (int j = 0; j < 4; j++) {
            // pass 1: qh · Khi
#pragma unroll
            for (int g = 0; g < 4; g++) {
                const uint32_t boff = (uint32_t)(g * 16) * AST + j * 32 + fragoff;
                uint32_t mh[4];
                ldmx4(mh, uKhi + boff);
                uint32_t b0[2] = {mh[0], mh[2]}, b1[2] = {mh[1], mh[3]};
                mma_f16(sc[2 * g + 0], qh[j], b0);
                mma_f16(sc[2 * g + 1], qh[j], b1);
            }
            // pass 2: qh · Klo
#pragma unroll
            for (int g = 0; g < 4; g++) {
                const uint32_t boff = (uint32_t)(g * 16) * AST + j * 32 + fragoff;
                uint32_t ml[4];
                ldmx4(ml, uKlo + boff);
                uint32_t b0[2] = {ml[0], ml[2]}, b1[2] = {ml[1], ml[3]};
                mma_f16(sc[2 * g + 0], qh[j], b0);
                mma_f16(sc[2 * g + 1], qh[j], b1);
            }
            // pass 3: ql · Khi (reload hi frags)
#pragma unroll
            for (int g = 0; g < 4; g++) {
                const uint32_t boff = (uint32_t)(g * 16) * AST + j * 32 + fragoff;
                uint32_t mh[4];
                ldmx4(mh, uKhi + boff);
                uint32_t b0[2] = {mh[0], mh[2]}, b1[2] = {mh[1], mh[3]};
                mma_f16(sc[2 * g + 0], ql[j], b0);
                mma_f16(sc[2 * g + 1], ql[j], b1);
            }
        }

        // ---- online softmax ----
        float mx0 = -1e30f, mx1 = -1e30f;
#pragma unroll
        for (int i = 0; i < 8; i++) {
            mx0 = fmaxf(mx0, fmaxf(sc[i][0], sc[i][1]));
            mx1 = fmaxf(mx1, fmaxf(sc[i][2], sc[i][3]));
        }
        mx0 = fmaxf(mx0, __shfl_xor_sync(0xffffffffu, mx0, 1));
        mx0 = fmaxf(mx0, __shfl_xor_sync(0xffffffffu, mx0, 2));
        mx1 = fmaxf(mx1, __shfl_xor_sync(0xffffffffu, mx1, 1));
        mx1 = fmaxf(mx1, __shfl_xor_sync(0xffffffffu, mx1, 2));
        const float mn0 = fmaxf(m0, mx0);
        const float mn1 = fmaxf(m1, mx1);
        const float c0 = __expf(m0 - mn0);
        const float c1 = __expf(m1 - mn1);
        float rs0 = 0.f, rs1 = 0.f;
#pragma unroll
        for (int i = 0; i < 8; i++) {
            sc[i][0] = __expf(sc[i][0] - mn0);
            sc[i][1] = __expf(sc[i][1] - mn0);
            sc[i][2] = __expf(sc[i][2] - mn1);
            sc[i][3] = __expf(sc[i][3] - mn1);
            rs0 += sc[i][0] + sc[i][1];
            rs1 += sc[i][2] + sc[i][3];
        }
        rs0 += __shfl_xor_sync(0xffffffffu, rs0, 1);
        rs0 += __shfl_xor_sync(0xffffffffu, rs0, 2);
        rs1 += __shfl_xor_sync(0xffffffffu, rs1, 1);
        rs1 += __shfl_xor_sync(0xffffffffu, rs1, 2);
        l0 = l0 * c0 + rs0;
        l1 = l1 * c1 + rs1;
        m0 = mn0;
        m1 = mn1;
#pragma unroll
        for (int i = 0; i < 8; i++) {
            o[i][0] *= c0; o[i][1] *= c0;
            o[i][2] *= c1; o[i][3] *= c1;
        }

        // ---- repack P hi only (C-frag -> A-frag) ----
        uint32_t ph[4][4];
#pragma unroll
        for (int j = 0; j < 4; j++) {
            ph[j][0] = pack_h(sc[2 * j][0],     sc[2 * j][1]);
            ph[j][1] = pack_h(sc[2 * j][2],     sc[2 * j][3]);
            ph[j][2] = pack_h(sc[2 * j + 1][0], sc[2 * j + 1][1]);
            ph[j][3] = pack_h(sc[2 * j + 1][2], sc[2 * j + 1][3]);
        }

        // ---- O += P V (1-MMA, acc distance 8 across g) ----
#pragma unroll
        for (int j = 0; j < 4; j++) {
#pragma unroll
            for (int g = 0; g < 4; g++) {
                const uint32_t voff = (uint32_t)(j * 16) * AST + g * 32 + fragoff;
                uint32_t mh[4];
                ldmx4t(mh, uVhi + voff);
                uint32_t b0[2] = {mh[0], mh[1]}, b1[2] = {mh[2], mh[3]};
                mma_f16(o[2 * g + 0], ph[j], b0);
                mma_f16(o[2 * g + 1], ph[j], b1);
            }
        }
    }

    // ---- epilogue: write hi plane only ----
    const float inv0 = 1.f / l0;
    const float inv1 = 1.f / l1;
    const int r0 = qt * 128 + warp * 16 + (lane >> 2);
    const size_t base0 = ((size_t)b * Ss + r0) * Dd + headoff + (lane & 3) * 2;
    const size_t base1 = base0 + (size_t)8 * Dd;
#pragma unroll
    for (int nt = 0; nt < 8; nt++) {
        ((uint32_t*)ohi)[(base0 + nt * 8) / 2] = pack_h(o[nt][0] * inv0, o[nt][1] * inv0);
        ((uint32_t*)ohi)[(base1 + nt * 8) / 2] = pack_h(o[nt][2] * inv1, o[nt][3] * inv1);
    }
}

// ---------------------------------------------------------------------------
extern "C" void kernel_launch(void* const* d_in, const int* in_sizes, int n_in,
                              void* d_out, int out_size)
{
    (void)in_sizes; (void)n_in; (void)out_size;
    const float* x  = (const float*)d_in[0];
    const float* w1 = (const float*)d_in[1];
    const float* b1 = (const float*)d_in[2];
    const float* w2 = (const float*)d_in[3];
    const float* b2 = (const float*)d_in[4];
    float* out = (float*)d_out;

    __half *xhi, *xlo, *w1hi, *w1lo, *w2hi, *qhi, *qlo, *ahi;
    cudaGetSymbolAddress((void**)&xhi, g_xhi);
    cudaGetSymbolAddress((void**)&xlo, g_xlo);
    cudaGetSymbolAddress((void**)&w1hi, g_w1hi);
    cudaGetSymbolAddress((void**)&w1lo, g_w1lo);
    cudaGetSymbolAddress((void**)&w2hi, g_w2hi);
    cudaGetSymbolAddress((void**)&qhi, g_qkvhi);
    cudaGetSymbolAddress((void**)&qlo, g_qkvlo);
    cudaGetSymbolAddress((void**)&ahi, g_ahi);

    cudaFuncSetAttribute(gemm_hf<0>, cudaFuncAttributeMaxDynamicSharedMemorySize, GEMM_SMEM);
    cudaFuncSetAttribute(gemm_hf<1>, cudaFuncAttributeMaxDynamicSharedMemorySize, GEMM_SMEM);
    cudaFuncSetAttribute(flash2, cudaFuncAttributeMaxDynamicSharedMemorySize, ATTN_SMEM);

    // pre-convert
    split_f32<<<(MM * Dd / 2 + 255) / 256, 256>>>(x, xhi, xlo, MM * Dd / 2);
    transpose_split<<<dim3(N1 / 32, Dd / 64), 256>>>(w1, w1hi, w1lo, Dd, N1, 1);
    transpose_split<<<dim3(Dd / 32, Dd / 64), 256>>>(w2, w2hi, nullptr, Dd, Dd, 0);

    // 1) QKV projection -> fp16 planes:
    //    Q cols [0,1024):      3-MMA, hi+lo out  (score path: full precision)
    //    K cols [1024,2048):   3-MMA, hi+lo out  (score path: full precision)
    //    V cols [2048,3072):   1-MMA, hi out     (value path: safe cut)
    gemm_hf<1><<<dim3(N1 / 128, MM / 128), 256, GEMM_SMEM>>>(
        xhi, xlo, w1hi, w1lo, b1, nullptr, qhi, qlo, MM, N1, Dd,
        /*n3lim=*/2 * Dd, /*alo=*/0, 2 * Dd, /*wlo=*/0, 2 * Dd);
    // 2) attention (QK 3-MMA, PV 1-MMA) -> a hi plane
    flash2<<<dim3(Ss / 128, Bb * Hh), 256, ATTN_SMEM>>>(qhi, qlo, ahi);
    // 3) output projection (1-MMA pure fp16) -> fp32 out
    gemm_hf<0><<<dim3(Dd / 128, MM / 128), 256, GEMM_SMEM>>>(
        ahi, nullptr, w2hi, nullptr, b2, out, nullptr, nullptr, MM, Dd, Dd,
        /*n3lim=*/0, /*alo=*/0, 0, /*wlo=*/0, 0);
}